// round 1
// baseline (speedup 1.0000x reference)
#include <cuda_runtime.h>

// ---------------- constants ----------------
#define NB      8
#define CI      256
#define HW      1600
#define DM      128
#define NHEAD   8
#define DH      16
#define NROWS   (NB*HW)        // 12800
#define NCLOUD  32768

// ---------------- device scratch (no allocation allowed) ----------------
__device__ float g_tok [NROWS*DM];     // l2-normalized image tokens
__device__ float g_attn[NROWS*DM];     // attention output
__device__ float g_imgacc[NB*CI];      // gem partial sums (image)
__device__ float g_seg  [NB*DM];       // gem partial sums (cloud)
__device__ float g_cnt  [NB];          // cloud counts

typedef unsigned long long u64;

// ---------------- packed f32x2 helpers (sm_103a) ----------------
__device__ __forceinline__ u64 fma2(u64 a, u64 b, u64 c){
  u64 d; asm("fma.rn.f32x2 %0, %1, %2, %3;" : "=l"(d) : "l"(a), "l"(b), "l"(c)); return d;
}
__device__ __forceinline__ u64 mul2(u64 a, u64 b){
  u64 d; asm("mul.rn.f32x2 %0, %1, %2;" : "=l"(d) : "l"(a), "l"(b)); return d;
}
__device__ __forceinline__ u64 pack2(float x, float y){
  u64 d; asm("mov.b64 %0, {%1, %2};" : "=l"(d) : "f"(x), "f"(y)); return d;
}
__device__ __forceinline__ float2 unpack2(u64 u){
  float2 f; asm("mov.b64 {%0, %1}, %2;" : "=f"(f.x), "=f"(f.y) : "l"(u)); return f;
}

// exp(t) for |t| <= ~0.26 : degree-6 Taylor, rel err ~1e-8, 6 FMA, no MUFU
__device__ __forceinline__ float exp_small(float t){
  float p = fmaf(t, 1.38888889e-3f, 8.33333333e-3f);
  p = fmaf(t, p, 4.16666667e-2f);
  p = fmaf(t, p, 1.66666667e-1f);
  p = fmaf(t, p, 0.5f);
  p = fmaf(t, p, 1.0f);
  p = fmaf(t, p, 1.0f);
  return p;
}

// ---------------- K0: zero accumulators ----------------
__global__ void zero_kernel(){
  int i = blockIdx.x*256 + threadIdx.x;
  if (i < NB*CI) g_imgacc[i] = 0.f;
  if (i < NB*DM) g_seg[i]    = 0.f;
  if (i < NB)    g_cnt[i]    = 0.f;
}

// ---------------- K1: x = einsum(bchw,cd)+b1, then rowwise l2norm -> g_tok ----
// rows r = (b,p) : A[r,k] = img[b*CI*HW + k*HW + p]  (K=256, N=128)
// block: 64 rows x 128 cols, 256 threads, 8x4 micro-tile per thread
__global__ __launch_bounds__(256) void gemm1_kernel(const float* __restrict__ img,
                                                    const float* __restrict__ W1,
                                                    const float* __restrict__ b1){
  __shared__ float As[32][64];    // [k][r]
  __shared__ float Ws[32][128];   // [k][c]
  int tile = blockIdx.x;                // 200 tiles of 64 rows (1600%64==0 -> no batch crossing)
  int b = tile / 25;
  int pbase = (tile % 25) * 64;
  const float* Ab = img + b*CI*HW + pbase;
  int tid = threadIdx.x;
  int rgrp = tid >> 5, lane = tid & 31;
  float acc[8][4];
  #pragma unroll
  for (int i=0;i<8;i++){ acc[i][0]=0.f; acc[i][1]=0.f; acc[i][2]=0.f; acc[i][3]=0.f; }

  for (int kt=0; kt<8; kt++){
    __syncthreads();
    #pragma unroll
    for (int it=0; it<8; it++){
      int idx = tid + it*256;
      int r = idx & 63, k = idx >> 6;
      As[k][r] = Ab[(kt*32+k)*HW + r];
    }
    #pragma unroll
    for (int it=0; it<4; it++){
      int idx = tid + it*256;
      int c4 = idx & 31, k = idx >> 5;
      *(float4*)&Ws[k][c4*4] = *(const float4*)(W1 + (kt*32+k)*DM + c4*4);
    }
    __syncthreads();
    #pragma unroll 8
    for (int k=0;k<32;k++){
      float4 w  = *(float4*)&Ws[k][lane*4];
      float4 a0 = *(float4*)&As[k][rgrp*8];
      float4 a1 = *(float4*)&As[k][rgrp*8+4];
      float a[8] = {a0.x,a0.y,a0.z,a0.w,a1.x,a1.y,a1.z,a1.w};
      #pragma unroll
      for (int i=0;i<8;i++){
        acc[i][0] = fmaf(a[i], w.x, acc[i][0]);
        acc[i][1] = fmaf(a[i], w.y, acc[i][1]);
        acc[i][2] = fmaf(a[i], w.z, acc[i][2]);
        acc[i][3] = fmaf(a[i], w.w, acc[i][3]);
      }
    }
  }
  float4 bb = *(const float4*)(b1 + lane*4);
  int Rbase = tile*64 + rgrp*8;
  #pragma unroll
  for (int i=0;i<8;i++){
    float x0 = acc[i][0]+bb.x, x1 = acc[i][1]+bb.y, x2 = acc[i][2]+bb.z, x3 = acc[i][3]+bb.w;
    float sq = x0*x0 + x1*x1 + x2*x2 + x3*x3;
    #pragma unroll
    for (int off=16; off; off>>=1) sq += __shfl_xor_sync(0xffffffffu, sq, off);
    float inv = 1.0f / fmaxf(sqrtf(sq), 1e-12f);
    *(float4*)(g_tok + (Rbase+i)*DM + lane*4) = make_float4(x0*inv, x1*inv, x2*inv, x3*inv);
  }
}

// ---------------- K3: full self-attention per (b,h), dh=16 --------------------
// |score| <= 0.25 (unit-norm tokens) -> no max subtraction, poly exp.
// q=k=v: key tile registers reused for score and V-accumulate.
// block = 128 threads, 1 query/thread; keys streamed in tiles of 32 via smem.
__global__ __launch_bounds__(128) void attn_kernel(){
  __shared__ float sK[32*16];
  const float* tok = g_tok;
  int b = blockIdx.z, h = blockIdx.y;
  int n = blockIdx.x*128 + threadIdx.x;
  bool active = (n < HW);
  const float* kbase = tok + b*HW*DM + h*DH;

  u64 q2[8];
  #pragma unroll
  for (int i=0;i<8;i++) q2[i] = 0ULL;
  if (active){
    const ulonglong2* qp = (const ulonglong2*)(kbase + n*DM);
    u64 qs = pack2(0.25f, 0.25f);               // fold dh^-0.5 into q
    #pragma unroll
    for (int i=0;i<4;i++){
      ulonglong2 v = qp[i];
      q2[2*i]   = mul2(v.x, qs);
      q2[2*i+1] = mul2(v.y, qs);
    }
  }
  u64 acc2[8];
  #pragma unroll
  for (int i=0;i<8;i++) acc2[i] = 0ULL;
  float l = 0.f;

  int jload = threadIdx.x >> 2, c4 = threadIdx.x & 3;
  for (int kt=0; kt<50; kt++){
    __syncthreads();
    *(float4*)(sK + jload*16 + c4*4) = *(const float4*)(kbase + (kt*32 + jload)*DM + c4*4);
    __syncthreads();
    #pragma unroll 8
    for (int j=0;j<32;j++){
      const ulonglong2* kp = (const ulonglong2*)(sK + j*16);
      ulonglong2 ka = kp[0], kb = kp[1], kc = kp[2], kd = kp[3];
      u64 s2 = fma2(q2[0], ka.x, 0ULL);
      s2 = fma2(q2[1], ka.y, s2);
      s2 = fma2(q2[2], kb.x, s2);
      s2 = fma2(q2[3], kb.y, s2);
      s2 = fma2(q2[4], kc.x, s2);
      s2 = fma2(q2[5], kc.y, s2);
      s2 = fma2(q2[6], kd.x, s2);
      s2 = fma2(q2[7], kd.y, s2);
      float2 sf = unpack2(s2);
      float e = exp_small(sf.x + sf.y);
      l += e;
      u64 e2 = pack2(e, e);
      acc2[0] = fma2(e2, ka.x, acc2[0]);
      acc2[1] = fma2(e2, ka.y, acc2[1]);
      acc2[2] = fma2(e2, kb.x, acc2[2]);
      acc2[3] = fma2(e2, kb.y, acc2[3]);
      acc2[4] = fma2(e2, kc.x, acc2[4]);
      acc2[5] = fma2(e2, kc.y, acc2[5]);
      acc2[6] = fma2(e2, kd.x, acc2[6]);
      acc2[7] = fma2(e2, kd.y, acc2[7]);
    }
  }
  if (active){
    float inv = 1.0f / l;
    float o[16];
    #pragma unroll
    for (int i=0;i<8;i++){ float2 a = unpack2(acc2[i]); o[2*i]=a.x*inv; o[2*i+1]=a.y*inv; }
    float* op = g_attn + b*HW*DM + h*DH + n*DM;
    #pragma unroll
    for (int i=0;i<4;i++)
      *(float4*)(op + i*4) = make_float4(o[4*i], o[4*i+1], o[4*i+2], o[4*i+3]);
  }
}

// ---------------- K4: img_out = attn @ W2 + b2, transposed write + GeM partials
// rows r=(b,p) 12800, K=128, N=256 split into 2 col-tiles of 128.
__global__ __launch_bounds__(256) void gemm2_kernel(const float* __restrict__ W2,
                                                    const float* __restrict__ b2,
                                                    float* __restrict__ img_out){
  __shared__ float As[64][33];    // [r][k], padded
  __shared__ float Ws[32][128];
  __shared__ float colsum[128];
  int tile = blockIdx.x, ct = blockIdx.y;
  int b = tile / 25, pbase = (tile % 25) * 64;
  int tid = threadIdx.x, rgrp = tid >> 5, lane = tid & 31;
  if (tid < 128) colsum[tid] = 0.f;
  float acc[8][4];
  #pragma unroll
  for (int i=0;i<8;i++){ acc[i][0]=0.f; acc[i][1]=0.f; acc[i][2]=0.f; acc[i][3]=0.f; }

  for (int kt=0; kt<4; kt++){
    __syncthreads();
    #pragma unroll
    for (int it=0; it<2; it++){
      int idx = tid + it*256;
      int k4 = idx & 7, r = idx >> 3;
      float4 v = *(const float4*)(g_attn + (tile*64 + r)*DM + kt*32 + k4*4);
      As[r][k4*4+0]=v.x; As[r][k4*4+1]=v.y; As[r][k4*4+2]=v.z; As[r][k4*4+3]=v.w;
    }
    #pragma unroll
    for (int it=0; it<4; it++){
      int idx = tid + it*256;
      int c4 = idx & 31, k = idx >> 5;
      *(float4*)&Ws[k][c4*4] = *(const float4*)(W2 + (kt*32+k)*CI + ct*128 + c4*4);
    }
    __syncthreads();
    #pragma unroll 8
    for (int k=0;k<32;k++){
      float4 w = *(float4*)&Ws[k][lane*4];
      #pragma unroll
      for (int i=0;i<8;i++){
        float a = As[rgrp*8+i][k];      // warp-uniform broadcast
        acc[i][0] = fmaf(a, w.x, acc[i][0]);
        acc[i][1] = fmaf(a, w.y, acc[i][1]);
        acc[i][2] = fmaf(a, w.z, acc[i][2]);
        acc[i][3] = fmaf(a, w.w, acc[i][3]);
      }
    }
  }
  float4 bb = *(const float4*)(b2 + ct*128 + lane*4);
  float bv[4] = {bb.x, bb.y, bb.z, bb.w};
  #pragma unroll
  for (int j=0;j<4;j++){
    float part = 0.f; float vs[8];
    #pragma unroll
    for (int i=0;i<8;i++){
      float v = acc[i][j] + bv[j];
      vs[i] = v;
      float c = fmaxf(v, 1e-6f);
      part = fmaf(c*c, c, part);
    }
    atomicAdd(&colsum[lane*4+j], part);
    int cg = ct*128 + lane*4 + j;
    float* dst = img_out + b*CI*HW + cg*HW + pbase + rgrp*8;
    *(float4*)(dst)     = make_float4(vs[0],vs[1],vs[2],vs[3]);
    *(float4*)(dst + 4) = make_float4(vs[4],vs[5],vs[6],vs[7]);
  }
  __syncthreads();
  if (tid < 128) atomicAdd(&g_imgacc[b*CI + ct*128 + tid], colsum[tid]);
}

// ---------------- K7: cloud l2norm + segmented clamp^3 sum -------------------
__global__ __launch_bounds__(256) void cloud_kernel(const float* __restrict__ cf,
                                                    const int* __restrict__ bids,
                                                    float* __restrict__ cloud_out){
  __shared__ float sseg[NB*DM];
  __shared__ float scnt[NB];
  int tid = threadIdx.x;
  for (int i=tid; i<NB*DM; i+=256) sseg[i] = 0.f;
  if (tid < NB) scnt[tid] = 0.f;
  __syncthreads();
  int w = tid >> 5, lane = tid & 31;
  int rbase = blockIdx.x*256 + w*32;
  for (int i=0;i<32;i++){
    int row = rbase + i;
    int bid = bids[row];
    float4 v = *(const float4*)(cf + row*DM + lane*4);
    float sq = v.x*v.x + v.y*v.y + v.z*v.z + v.w*v.w;
    #pragma unroll
    for (int off=16; off; off>>=1) sq += __shfl_xor_sync(0xffffffffu, sq, off);
    float inv = 1.0f / fmaxf(sqrtf(sq), 1e-12f);
    float x0=v.x*inv, x1=v.y*inv, x2=v.z*inv, x3=v.w*inv;
    *(float4*)(cloud_out + row*DM + lane*4) = make_float4(x0,x1,x2,x3);
    float c0=fmaxf(x0,1e-6f), c1=fmaxf(x1,1e-6f), c2=fmaxf(x2,1e-6f), c3=fmaxf(x3,1e-6f);
    float* sp = sseg + bid*DM + lane*4;
    atomicAdd(sp+0, c0*c0*c0);
    atomicAdd(sp+1, c1*c1*c1);
    atomicAdd(sp+2, c2*c2*c2);
    atomicAdd(sp+3, c3*c3*c3);
    if (lane == 0) atomicAdd(&scnt[bid], 1.0f);
  }
  __syncthreads();
  for (int i=tid; i<NB*DM; i+=256) atomicAdd(&g_seg[i], sseg[i]);
  if (tid < NB) atomicAdd(&g_cnt[tid], scnt[tid]);
}

// ---------------- K8: finalize GeM outputs ----------------
__global__ void finalize_kernel(float* __restrict__ image_gem, float* __restrict__ cloud_gem){
  int i = blockIdx.x*256 + threadIdx.x;
  if (i < NB*CI) image_gem[i] = cbrtf(g_imgacc[i] * (1.0f/1600.0f));
  if (i < NB*DM) cloud_gem[i] = cbrtf(g_seg[i] / fmaxf(g_cnt[i>>7], 1.0f));
}

// ---------------- launch ----------------
extern "C" void kernel_launch(void* const* d_in, const int* in_sizes, int n_in,
                              void* d_out, int out_size){
  const float* img  = (const float*)d_in[0];
  const float* cf   = (const float*)d_in[1];
  const int*   bids = (const int*)  d_in[2];
  const float* W1   = (const float*)d_in[3];
  const float* b1   = (const float*)d_in[4];
  const float* W2   = (const float*)d_in[5];
  const float* b2   = (const float*)d_in[6];

  float* out       = (float*)d_out;
  float* img_out   = out;                                  // 8*256*1600
  float* cloud_out = out + (size_t)NB*CI*HW;               // 32768*128
  float* image_gem = cloud_out + (size_t)NCLOUD*DM;        // 2048
  float* cloud_gem = image_gem + NB*CI;                    // 1024

  zero_kernel<<<8, 256>>>();
  gemm1_kernel<<<200, 256>>>(img, W1, b1);
  attn_kernel<<<dim3(13, NHEAD, NB), 128>>>();
  gemm2_kernel<<<dim3(200, 2), 256>>>(W2, b2, img_out);
  cloud_kernel<<<NCLOUD/256, 256>>>(cf, bids, cloud_out);
  finalize_kernel<<<8, 256>>>(image_gem, cloud_gem);
}

// round 2
// speedup vs baseline: 1.1639x; 1.1639x over previous
#include <cuda_runtime.h>

// ---------------- constants ----------------
#define NB      8
#define CI      256
#define HW      1600
#define DM      128
#define NHEAD   8
#define DH      16
#define NROWS   (NB*HW)        // 12800
#define NCLOUD  32768

// ---------------- device scratch (no allocation allowed) ----------------
__device__ float g_tok [NROWS*DM];     // l2-normalized image tokens
__device__ float g_attn[NROWS*DM];     // attention output
__device__ float g_imgacc[NB*CI];      // gem partial sums (image)
__device__ float g_seg  [NB*DM];       // gem partial sums (cloud)
__device__ float g_cnt  [NB];          // cloud counts

typedef unsigned long long u64;

// ---------------- packed f32x2 helpers (sm_103a) ----------------
__device__ __forceinline__ u64 fma2(u64 a, u64 b, u64 c){
  u64 d; asm("fma.rn.f32x2 %0, %1, %2, %3;" : "=l"(d) : "l"(a), "l"(b), "l"(c)); return d;
}
__device__ __forceinline__ u64 mul2(u64 a, u64 b){
  u64 d; asm("mul.rn.f32x2 %0, %1, %2;" : "=l"(d) : "l"(a), "l"(b)); return d;
}
__device__ __forceinline__ u64 add2(u64 a, u64 b){
  u64 d; asm("add.rn.f32x2 %0, %1, %2;" : "=l"(d) : "l"(a), "l"(b)); return d;
}
__device__ __forceinline__ u64 pack2(float x, float y){
  u64 d; asm("mov.b64 %0, {%1, %2};" : "=l"(d) : "f"(x), "f"(y)); return d;
}
__device__ __forceinline__ float2 unpack2(u64 u){
  float2 f; asm("mov.b64 {%0, %1}, %2;" : "=f"(f.x), "=f"(f.y) : "l"(u)); return f;
}

// ---------------- K0: zero accumulators ----------------
__global__ void zero_kernel(){
  int i = blockIdx.x*256 + threadIdx.x;
  if (i < NB*CI) g_imgacc[i] = 0.f;
  if (i < NB*DM) g_seg[i]    = 0.f;
  if (i < NB)    g_cnt[i]    = 0.f;
}

// ---------------- K1: x = einsum(bchw,cd)+b1, rowwise l2norm -> g_tok --------
__global__ __launch_bounds__(256) void gemm1_kernel(const float* __restrict__ img,
                                                    const float* __restrict__ W1,
                                                    const float* __restrict__ b1){
  __shared__ float As[32][64];    // [k][r]
  __shared__ float Ws[32][128];   // [k][c]
  int tile = blockIdx.x;
  int b = tile / 25;
  int pbase = (tile % 25) * 64;
  const float* Ab = img + b*CI*HW + pbase;
  int tid = threadIdx.x;
  int rgrp = tid >> 5, lane = tid & 31;
  float acc[8][4];
  #pragma unroll
  for (int i=0;i<8;i++){ acc[i][0]=0.f; acc[i][1]=0.f; acc[i][2]=0.f; acc[i][3]=0.f; }

  for (int kt=0; kt<8; kt++){
    __syncthreads();
    #pragma unroll
    for (int it=0; it<8; it++){
      int idx = tid + it*256;
      int r = idx & 63, k = idx >> 6;
      As[k][r] = Ab[(kt*32+k)*HW + r];
    }
    #pragma unroll
    for (int it=0; it<4; it++){
      int idx = tid + it*256;
      int c4 = idx & 31, k = idx >> 5;
      *(float4*)&Ws[k][c4*4] = *(const float4*)(W1 + (kt*32+k)*DM + c4*4);
    }
    __syncthreads();
    #pragma unroll 8
    for (int k=0;k<32;k++){
      float4 w  = *(float4*)&Ws[k][lane*4];
      float4 a0 = *(float4*)&As[k][rgrp*8];
      float4 a1 = *(float4*)&As[k][rgrp*8+4];
      float a[8] = {a0.x,a0.y,a0.z,a0.w,a1.x,a1.y,a1.z,a1.w};
      #pragma unroll
      for (int i=0;i<8;i++){
        acc[i][0] = fmaf(a[i], w.x, acc[i][0]);
        acc[i][1] = fmaf(a[i], w.y, acc[i][1]);
        acc[i][2] = fmaf(a[i], w.z, acc[i][2]);
        acc[i][3] = fmaf(a[i], w.w, acc[i][3]);
      }
    }
  }
  float4 bb = *(const float4*)(b1 + lane*4);
  int Rbase = tile*64 + rgrp*8;
  #pragma unroll
  for (int i=0;i<8;i++){
    float x0 = acc[i][0]+bb.x, x1 = acc[i][1]+bb.y, x2 = acc[i][2]+bb.z, x3 = acc[i][3]+bb.w;
    float sq = x0*x0 + x1*x1 + x2*x2 + x3*x3;
    #pragma unroll
    for (int off=16; off; off>>=1) sq += __shfl_xor_sync(0xffffffffu, sq, off);
    float inv = 1.0f / fmaxf(sqrtf(sq), 1e-12f);
    *(float4*)(g_tok + (Rbase+i)*DM + lane*4) = make_float4(x0*inv, x1*inv, x2*inv, x3*inv);
  }
}

// ---------------- K3: full self-attention per (b,h), dh=16 --------------------
// 2 queries/thread; packed f32x2 score/exp/acc; double-buffered K tile, 1 sync/tile.
// |score| <= 0.25 (unit-norm tokens) -> no max subtraction, degree-6 Taylor exp.
__global__ __launch_bounds__(128) void attn_kernel(){
  __shared__ float sK[2][32*16];
  int b = blockIdx.z, h = blockIdx.y;
  int tid = threadIdx.x;
  int n0 = blockIdx.x*256 + tid;
  int n1 = n0 + 128;
  bool act0 = (n0 < HW), act1 = (n1 < HW);
  const float* kbase = g_tok + b*HW*DM + h*DH;

  u64 q0[8], q1[8];
  #pragma unroll
  for (int i=0;i<8;i++){ q0[i]=0ULL; q1[i]=0ULL; }
  {
    u64 qs = pack2(0.25f, 0.25f);               // fold dh^-0.5 into q
    if (act0){
      const ulonglong2* qp = (const ulonglong2*)(kbase + n0*DM);
      #pragma unroll
      for (int i=0;i<4;i++){ ulonglong2 v = qp[i]; q0[2*i]=mul2(v.x,qs); q0[2*i+1]=mul2(v.y,qs); }
    }
    if (act1){
      const ulonglong2* qp = (const ulonglong2*)(kbase + n1*DM);
      #pragma unroll
      for (int i=0;i<4;i++){ ulonglong2 v = qp[i]; q1[2*i]=mul2(v.x,qs); q1[2*i+1]=mul2(v.y,qs); }
    }
  }
  u64 acc0[8], acc1[8];
  #pragma unroll
  for (int i=0;i<8;i++){ acc0[i]=0ULL; acc1[i]=0ULL; }
  u64 l2 = 0ULL;

  // packed Taylor coefficients for exp(t), |t|<=0.26
  const u64 C6 = pack2(1.38888889e-3f, 1.38888889e-3f);
  const u64 C5 = pack2(8.33333333e-3f, 8.33333333e-3f);
  const u64 C4 = pack2(4.16666667e-2f, 4.16666667e-2f);
  const u64 C3 = pack2(1.66666667e-1f, 1.66666667e-1f);
  const u64 C2 = pack2(0.5f, 0.5f);
  const u64 C1 = pack2(1.0f, 1.0f);

  int jload = tid >> 2, c4 = tid & 3;
  const float* gload = kbase + jload*DM + c4*4;

  // prologue: tile 0 -> buf 0
  {
    float4 v = *(const float4*)(gload);
    *(float4*)(&sK[0][jload*16 + c4*4]) = v;
  }
  __syncthreads();

  for (int kt=0; kt<50; kt++){
    float4 vn;
    if (kt < 49) vn = *(const float4*)(gload + (kt+1)*32*DM);
    const float* buf = sK[kt & 1];
    #pragma unroll 8
    for (int j=0;j<32;j++){
      const ulonglong2* kp = (const ulonglong2*)(buf + j*16);
      ulonglong2 ka = kp[0], kb = kp[1], kc = kp[2], kd = kp[3];
      u64 s0 = mul2(q0[0], ka.x);
      s0 = fma2(q0[1], ka.y, s0);
      s0 = fma2(q0[2], kb.x, s0);
      s0 = fma2(q0[3], kb.y, s0);
      s0 = fma2(q0[4], kc.x, s0);
      s0 = fma2(q0[5], kc.y, s0);
      s0 = fma2(q0[6], kd.x, s0);
      s0 = fma2(q0[7], kd.y, s0);
      u64 s1 = mul2(q1[0], ka.x);
      s1 = fma2(q1[1], ka.y, s1);
      s1 = fma2(q1[2], kb.x, s1);
      s1 = fma2(q1[3], kb.y, s1);
      s1 = fma2(q1[4], kc.x, s1);
      s1 = fma2(q1[5], kc.y, s1);
      s1 = fma2(q1[6], kd.x, s1);
      s1 = fma2(q1[7], kd.y, s1);
      float2 f0 = unpack2(s0);
      float2 f1 = unpack2(s1);
      u64 t = pack2(f0.x + f0.y, f1.x + f1.y);
      // packed exp: degree-6 Taylor
      u64 p = fma2(t, C6, C5);
      p = fma2(t, p, C4);
      p = fma2(t, p, C3);
      p = fma2(t, p, C2);
      p = fma2(t, p, C1);
      p = fma2(t, p, C1);
      l2 = add2(l2, p);
      float2 ef = unpack2(p);
      u64 e00 = pack2(ef.x, ef.x);
      u64 e11 = pack2(ef.y, ef.y);
      acc0[0] = fma2(e00, ka.x, acc0[0]);
      acc0[1] = fma2(e00, ka.y, acc0[1]);
      acc0[2] = fma2(e00, kb.x, acc0[2]);
      acc0[3] = fma2(e00, kb.y, acc0[3]);
      acc0[4] = fma2(e00, kc.x, acc0[4]);
      acc0[5] = fma2(e00, kc.y, acc0[5]);
      acc0[6] = fma2(e00, kd.x, acc0[6]);
      acc0[7] = fma2(e00, kd.y, acc0[7]);
      acc1[0] = fma2(e11, ka.x, acc1[0]);
      acc1[1] = fma2(e11, ka.y, acc1[1]);
      acc1[2] = fma2(e11, kb.x, acc1[2]);
      acc1[3] = fma2(e11, kb.y, acc1[3]);
      acc1[4] = fma2(e11, kc.x, acc1[4]);
      acc1[5] = fma2(e11, kc.y, acc1[5]);
      acc1[6] = fma2(e11, kd.x, acc1[6]);
      acc1[7] = fma2(e11, kd.y, acc1[7]);
    }
    if (kt < 49){
      // buf (kt+1)&1 was last read in iteration kt-1; safe to overwrite now
      *(float4*)(&sK[(kt+1) & 1][jload*16 + c4*4]) = vn;
    }
    __syncthreads();
  }

  float2 lf = unpack2(l2);
  if (act0){
    float inv = 1.0f / lf.x;
    float o[16];
    #pragma unroll
    for (int i=0;i<8;i++){ float2 a = unpack2(acc0[i]); o[2*i]=a.x*inv; o[2*i+1]=a.y*inv; }
    float* op = g_attn + b*HW*DM + h*DH + n0*DM;
    #pragma unroll
    for (int i=0;i<4;i++)
      *(float4*)(op + i*4) = make_float4(o[4*i], o[4*i+1], o[4*i+2], o[4*i+3]);
  }
  if (act1){
    float inv = 1.0f / lf.y;
    float o[16];
    #pragma unroll
    for (int i=0;i<8;i++){ float2 a = unpack2(acc1[i]); o[2*i]=a.x*inv; o[2*i+1]=a.y*inv; }
    float* op = g_attn + b*HW*DM + h*DH + n1*DM;
    #pragma unroll
    for (int i=0;i<4;i++)
      *(float4*)(op + i*4) = make_float4(o[4*i], o[4*i+1], o[4*i+2], o[4*i+3]);
  }
}

// ---------------- K4: img_out = attn @ W2 + b2, transposed write + GeM partials
__global__ __launch_bounds__(256) void gemm2_kernel(const float* __restrict__ W2,
                                                    const float* __restrict__ b2,
                                                    float* __restrict__ img_out){
  __shared__ float As[64][33];    // [r][k], padded
  __shared__ float Ws[32][128];
  __shared__ float colsum[128];
  int tile = blockIdx.x, ct = blockIdx.y;
  int b = tile / 25, pbase = (tile % 25) * 64;
  int tid = threadIdx.x, rgrp = tid >> 5, lane = tid & 31;
  if (tid < 128) colsum[tid] = 0.f;
  float acc[8][4];
  #pragma unroll
  for (int i=0;i<8;i++){ acc[i][0]=0.f; acc[i][1]=0.f; acc[i][2]=0.f; acc[i][3]=0.f; }

  for (int kt=0; kt<4; kt++){
    __syncthreads();
    #pragma unroll
    for (int it=0; it<2; it++){
      int idx = tid + it*256;
      int k4 = idx & 7, r = idx >> 3;
      float4 v = *(const float4*)(g_attn + (tile*64 + r)*DM + kt*32 + k4*4);
      As[r][k4*4+0]=v.x; As[r][k4*4+1]=v.y; As[r][k4*4+2]=v.z; As[r][k4*4+3]=v.w;
    }
    #pragma unroll
    for (int it=0; it<4; it++){
      int idx = tid + it*256;
      int c4 = idx & 31, k = idx >> 5;
      *(float4*)&Ws[k][c4*4] = *(const float4*)(W2 + (kt*32+k)*CI + ct*128 + c4*4);
    }
    __syncthreads();
    #pragma unroll 8
    for (int k=0;k<32;k++){
      float4 w = *(float4*)&Ws[k][lane*4];
      #pragma unroll
      for (int i=0;i<8;i++){
        float a = As[rgrp*8+i][k];
        acc[i][0] = fmaf(a, w.x, acc[i][0]);
        acc[i][1] = fmaf(a, w.y, acc[i][1]);
        acc[i][2] = fmaf(a, w.z, acc[i][2]);
        acc[i][3] = fmaf(a, w.w, acc[i][3]);
      }
    }
  }
  float4 bb = *(const float4*)(b2 + ct*128 + lane*4);
  float bv[4] = {bb.x, bb.y, bb.z, bb.w};
  #pragma unroll
  for (int j=0;j<4;j++){
    float part = 0.f; float vs[8];
    #pragma unroll
    for (int i=0;i<8;i++){
      float v = acc[i][j] + bv[j];
      vs[i] = v;
      float c = fmaxf(v, 1e-6f);
      part = fmaf(c*c, c, part);
    }
    atomicAdd(&colsum[lane*4+j], part);
    int cg = ct*128 + lane*4 + j;
    float* dst = img_out + b*CI*HW + cg*HW + pbase + rgrp*8;
    *(float4*)(dst)     = make_float4(vs[0],vs[1],vs[2],vs[3]);
    *(float4*)(dst + 4) = make_float4(vs[4],vs[5],vs[6],vs[7]);
  }
  __syncthreads();
  if (tid < 128) atomicAdd(&g_imgacc[b*CI + ct*128 + tid], colsum[tid]);
}

// ---------------- K7: cloud l2norm + segmented clamp^3 sum -------------------
__global__ __launch_bounds__(256) void cloud_kernel(const float* __restrict__ cf,
                                                    const int* __restrict__ bids,
                                                    float* __restrict__ cloud_out){
  __shared__ float sseg[NB*DM];
  __shared__ float scnt[NB];
  int tid = threadIdx.x;
  for (int i=tid; i<NB*DM; i+=256) sseg[i] = 0.f;
  if (tid < NB) scnt[tid] = 0.f;
  __syncthreads();
  int w = tid >> 5, lane = tid & 31;
  int rbase = blockIdx.x*256 + w*32;
  for (int i=0;i<32;i++){
    int row = rbase + i;
    int bid = bids[row];
    float4 v = *(const float4*)(cf + row*DM + lane*4);
    float sq = v.x*v.x + v.y*v.y + v.z*v.z + v.w*v.w;
    #pragma unroll
    for (int off=16; off; off>>=1) sq += __shfl_xor_sync(0xffffffffu, sq, off);
    float inv = 1.0f / fmaxf(sqrtf(sq), 1e-12f);
    float x0=v.x*inv, x1=v.y*inv, x2=v.z*inv, x3=v.w*inv;
    *(float4*)(cloud_out + row*DM + lane*4) = make_float4(x0,x1,x2,x3);
    float c0=fmaxf(x0,1e-6f), c1=fmaxf(x1,1e-6f), c2=fmaxf(x2,1e-6f), c3=fmaxf(x3,1e-6f);
    float* sp = sseg + bid*DM + lane*4;
    atomicAdd(sp+0, c0*c0*c0);
    atomicAdd(sp+1, c1*c1*c1);
    atomicAdd(sp+2, c2*c2*c2);
    atomicAdd(sp+3, c3*c3*c3);
    if (lane == 0) atomicAdd(&scnt[bid], 1.0f);
  }
  __syncthreads();
  for (int i=tid; i<NB*DM; i+=256) atomicAdd(&g_seg[i], sseg[i]);
  if (tid < NB) atomicAdd(&g_cnt[tid], scnt[tid]);
}

// ---------------- K8: finalize GeM outputs ----------------
__global__ void finalize_kernel(float* __restrict__ image_gem, float* __restrict__ cloud_gem){
  int i = blockIdx.x*256 + threadIdx.x;
  if (i < NB*CI) image_gem[i] = cbrtf(g_imgacc[i] * (1.0f/1600.0f));
  if (i < NB*DM) cloud_gem[i] = cbrtf(g_seg[i] / fmaxf(g_cnt[i>>7], 1.0f));
}

// ---------------- launch ----------------
extern "C" void kernel_launch(void* const* d_in, const int* in_sizes, int n_in,
                              void* d_out, int out_size){
  const float* img  = (const float*)d_in[0];
  const float* cf   = (const float*)d_in[1];
  const int*   bids = (const int*)  d_in[2];
  const float* W1   = (const float*)d_in[3];
  const float* b1   = (const float*)d_in[4];
  const float* W2   = (const float*)d_in[5];
  const float* b2   = (const float*)d_in[6];

  float* out       = (float*)d_out;
  float* img_out   = out;                                  // 8*256*1600
  float* cloud_out = out + (size_t)NB*CI*HW;               // 32768*128
  float* image_gem = cloud_out + (size_t)NCLOUD*DM;        // 2048
  float* cloud_gem = image_gem + NB*CI;                    // 1024

  zero_kernel<<<8, 256>>>();
  gemm1_kernel<<<200, 256>>>(img, W1, b1);
  attn_kernel<<<dim3(7, NHEAD, NB), 128>>>();
  gemm2_kernel<<<dim3(200, 2), 256>>>(W2, b2, img_out);
  cloud_kernel<<<NCLOUD/256, 256>>>(cf, bids, cloud_out);
  finalize_kernel<<<8, 256>>>(image_gem, cloud_gem);
}

// round 3
// speedup vs baseline: 1.7067x; 1.4663x over previous
#include <cuda_runtime.h>
#include <cstdint>

// ---------------- constants ----------------
#define NB      8
#define CI      256
#define HW      1600
#define DM      128
#define NHEAD   8
#define DH      16
#define NROWS   (NB*HW)        // 12800
#define NCLOUD  32768

// ---------------- device scratch ----------------
__device__ float g_tok [NROWS*DM];     // l2-normalized image tokens
__device__ float g_attn[NROWS*DM];     // attention output
__device__ float g_m0  [NB*NHEAD*DH];  // per (b,h) sum of v over keys
__device__ float g_imgacc[NB*CI];
__device__ float g_seg  [NB*DM];
__device__ float g_cnt  [NB];

typedef unsigned long long u64;

// ---------------- packed f32x2 helpers ----------------
__device__ __forceinline__ u64 fma2(u64 a, u64 b, u64 c){
  u64 d; asm("fma.rn.f32x2 %0, %1, %2, %3;" : "=l"(d) : "l"(a), "l"(b), "l"(c)); return d;
}
__device__ __forceinline__ u64 mul2(u64 a, u64 b){
  u64 d; asm("mul.rn.f32x2 %0, %1, %2;" : "=l"(d) : "l"(a), "l"(b)); return d;
}
__device__ __forceinline__ u64 add2(u64 a, u64 b){
  u64 d; asm("add.rn.f32x2 %0, %1, %2;" : "=l"(d) : "l"(a), "l"(b)); return d;
}
__device__ __forceinline__ u64 pack2(float x, float y){
  u64 d; asm("mov.b64 %0, {%1, %2};" : "=l"(d) : "f"(x), "f"(y)); return d;
}
__device__ __forceinline__ float2 unpack2(u64 u){
  float2 f; asm("mov.b64 {%0, %1}, %2;" : "=f"(f.x), "=f"(f.y) : "l"(u)); return f;
}

// ---------------- tf32 mma helpers ----------------
__device__ __forceinline__ uint32_t cvt_tf32(float f){
  uint32_t r; asm("cvt.rna.tf32.f32 %0, %1;" : "=r"(r) : "f"(f)); return r;
}
__device__ __forceinline__ void mma_tf32(float* c, const uint32_t* a, uint32_t b0, uint32_t b1){
  asm volatile("mma.sync.aligned.m16n8k8.row.col.f32.tf32.tf32.f32 "
      "{%0,%1,%2,%3}, {%4,%5,%6,%7}, {%8,%9}, {%0,%1,%2,%3};"
      : "+f"(c[0]), "+f"(c[1]), "+f"(c[2]), "+f"(c[3])
      : "r"(a[0]), "r"(a[1]), "r"(a[2]), "r"(a[3]), "r"(b0), "r"(b1));
}
__device__ __forceinline__ void sts_u32(uint32_t addr, uint32_t v){
  asm volatile("st.shared.b32 [%0], %1;" :: "r"(addr), "r"(v));
}
__device__ __forceinline__ uint32_t lds_u32(uint32_t addr){
  uint32_t v; asm volatile("ld.shared.b32 %0, [%1];" : "=r"(v) : "r"(addr)); return v;
}

// ---------------- K0: zero accumulators ----------------
__global__ void zero_kernel(){
  int i = blockIdx.x*256 + threadIdx.x;
  if (i < NB*CI) g_imgacc[i] = 0.f;
  if (i < NB*DM) g_seg[i]    = 0.f;
  if (i < NB)    g_cnt[i]    = 0.f;
}

// ---------------- K1: x = einsum(bchw,cd)+b1, rowwise l2norm -> g_tok --------
__global__ __launch_bounds__(256) void gemm1_kernel(const float* __restrict__ img,
                                                    const float* __restrict__ W1,
                                                    const float* __restrict__ b1){
  __shared__ float As[32][64];
  __shared__ float Ws[32][128];
  int tile = blockIdx.x;
  int b = tile / 25;
  int pbase = (tile % 25) * 64;
  const float* Ab = img + b*CI*HW + pbase;
  int tid = threadIdx.x;
  int rgrp = tid >> 5, lane = tid & 31;
  float acc[8][4];
  #pragma unroll
  for (int i=0;i<8;i++){ acc[i][0]=0.f; acc[i][1]=0.f; acc[i][2]=0.f; acc[i][3]=0.f; }

  for (int kt=0; kt<8; kt++){
    __syncthreads();
    #pragma unroll
    for (int it=0; it<8; it++){
      int idx = tid + it*256;
      int r = idx & 63, k = idx >> 6;
      As[k][r] = Ab[(kt*32+k)*HW + r];
    }
    #pragma unroll
    for (int it=0; it<4; it++){
      int idx = tid + it*256;
      int c4 = idx & 31, k = idx >> 5;
      *(float4*)&Ws[k][c4*4] = *(const float4*)(W1 + (kt*32+k)*DM + c4*4);
    }
    __syncthreads();
    #pragma unroll 8
    for (int k=0;k<32;k++){
      float4 w  = *(float4*)&Ws[k][lane*4];
      float4 a0 = *(float4*)&As[k][rgrp*8];
      float4 a1 = *(float4*)&As[k][rgrp*8+4];
      float a[8] = {a0.x,a0.y,a0.z,a0.w,a1.x,a1.y,a1.z,a1.w};
      #pragma unroll
      for (int i=0;i<8;i++){
        acc[i][0] = fmaf(a[i], w.x, acc[i][0]);
        acc[i][1] = fmaf(a[i], w.y, acc[i][1]);
        acc[i][2] = fmaf(a[i], w.z, acc[i][2]);
        acc[i][3] = fmaf(a[i], w.w, acc[i][3]);
      }
    }
  }
  float4 bb = *(const float4*)(b1 + lane*4);
  int Rbase = tile*64 + rgrp*8;
  #pragma unroll
  for (int i=0;i<8;i++){
    float x0 = acc[i][0]+bb.x, x1 = acc[i][1]+bb.y, x2 = acc[i][2]+bb.z, x3 = acc[i][3]+bb.w;
    float sq = x0*x0 + x1*x1 + x2*x2 + x3*x3;
    #pragma unroll
    for (int off=16; off; off>>=1) sq += __shfl_xor_sync(0xffffffffu, sq, off);
    float inv = 1.0f / fmaxf(sqrtf(sq), 1e-12f);
    *(float4*)(g_tok + (Rbase+i)*DM + lane*4) = make_float4(x0*inv, x1*inv, x2*inv, x3*inv);
  }
}

// ---------------- K2: M0[b,h,d] = sum over keys of v ----------------
__global__ __launch_bounds__(128) void m0_kernel(){
  int bh = blockIdx.x;                  // 64 blocks
  const float* base = g_tok + (bh>>3)*HW*DM + (bh&7)*DH;
  __shared__ float red[128];
  int tid = threadIdx.x;
  int d = tid & 15, seg = tid >> 4;     // 8 segments
  float s = 0.f;
  for (int t = seg; t < HW; t += 8) s += base[t*DM + d];
  red[tid] = s;
  __syncthreads();
  if (tid < 16){
    float a = 0.f;
    #pragma unroll
    for (int i=0;i<8;i++) a += red[tid + i*16];
    g_m0[bh*16 + tid] = a;
  }
}

// ---------------- K3: attention via tf32 mma.sync ----------------
// warp = 16 queries, CTA = 64 queries; grid (25, NHEAD, NB). exact tiling.
// S = (Q/4)K^T (mma), u = expm1(S) deg-5 poly, O = M0 + U*V (mma), l = 1600 + sum u.
#define KSTRIDE 20
__global__ __launch_bounds__(128) void attn_mma_kernel(){
  __shared__ float sK[2][64*KSTRIDE];          // key tile, stride-20 padded
  __shared__ uint32_t sP[4][16*12];            // per-warp P roundtrip (tf32 bits)
  int b = blockIdx.z, h = blockIdx.y;
  int tid = threadIdx.x, w = tid >> 5, lane = tid & 31;
  int gid = lane >> 2, tig = lane & 3;
  const float* base = g_tok + b*HW*DM + h*DH;  // token t, dim d at base[t*DM + d]
  int qbase = blockIdx.x*64 + w*16;

  // Q fragments (scaled by 0.25, rna-converted). a0:(gid,tig) a1:(gid+8,tig) a2:(gid,tig+4) a3:(gid+8,tig+4)
  uint32_t qa[2][4];
  #pragma unroll
  for (int kc=0; kc<2; kc++){
    qa[kc][0] = cvt_tf32(base[(qbase+gid  )*DM + kc*8 + tig    ] * 0.25f);
    qa[kc][1] = cvt_tf32(base[(qbase+gid+8)*DM + kc*8 + tig    ] * 0.25f);
    qa[kc][2] = cvt_tf32(base[(qbase+gid  )*DM + kc*8 + tig + 4] * 0.25f);
    qa[kc][3] = cvt_tf32(base[(qbase+gid+8)*DM + kc*8 + tig + 4] * 0.25f);
  }

  float oa[2][4];
  #pragma unroll
  for (int nt=0; nt<2; nt++){ oa[nt][0]=0.f; oa[nt][1]=0.f; oa[nt][2]=0.f; oa[nt][3]=0.f; }
  u64 lacc01 = 0ULL, lacc23 = 0ULL;

  const u64 C120 = pack2(8.3333333e-3f, 8.3333333e-3f);   // 1/120
  const u64 C24  = pack2(4.1666667e-2f, 4.1666667e-2f);   // 1/24
  const u64 C6   = pack2(1.6666667e-1f, 1.6666667e-1f);   // 1/6
  const u64 CH   = pack2(0.5f, 0.5f);
  const u64 C1   = pack2(1.0f, 1.0f);

  // K tile loading: 256 float4s per tile, 2 per thread
  int key0 = tid >> 2, q40 = tid & 3;          // first half: keys 0..31
  int key1 = key0 + 32;                        // second half: keys 32..63
  uint32_t pbase_a;
  {
    uint32_t* pp = &sP[w][0];
    pbase_a = (uint32_t)__cvta_generic_to_shared(pp);
  }

  // prologue: tile 0
  {
    float4 v0 = *(const float4*)(base + (key0)*DM + q40*4);
    float4 v1 = *(const float4*)(base + (key1)*DM + q40*4);
    *(float4*)&sK[0][key0*KSTRIDE + q40*4] = v0;
    *(float4*)&sK[0][key1*KSTRIDE + q40*4] = v1;
  }
  __syncthreads();

  for (int kb=0; kb<25; kb++){
    float4 n0, n1;
    if (kb < 24){
      n0 = *(const float4*)(base + ((kb+1)*64 + key0)*DM + q40*4);
      n1 = *(const float4*)(base + ((kb+1)*64 + key1)*DM + q40*4);
    }
    const float* kt = sK[kb & 1];

    #pragma unroll
    for (int ck=0; ck<8; ck++){
      int keyb = ck*8;
      // ---- scores S = Q K^T ----
      float c[4] = {0.f, 0.f, 0.f, 0.f};
      {
        // B frag (k-chunk kc): b0 = K[keyb+gid][kc*8+tig], b1 = +4 dims
        uint32_t b0 = __float_as_uint(kt[(keyb+gid)*KSTRIDE + tig    ]);
        uint32_t b1 = __float_as_uint(kt[(keyb+gid)*KSTRIDE + tig + 4]);
        mma_tf32(c, qa[0], b0, b1);
        uint32_t b2 = __float_as_uint(kt[(keyb+gid)*KSTRIDE + 8 + tig    ]);
        uint32_t b3 = __float_as_uint(kt[(keyb+gid)*KSTRIDE + 8 + tig + 4]);
        mma_tf32(c, qa[1], b2, b3);
      }
      // ---- u = expm1(t), deg-5, packed ----
      u64 t01 = pack2(c[0], c[1]);
      u64 t23 = pack2(c[2], c[3]);
      u64 w01 = fma2(t01, C120, C24);
      u64 w23 = fma2(t23, C120, C24);
      w01 = fma2(t01, w01, C6);
      w23 = fma2(t23, w23, C6);
      w01 = fma2(t01, w01, CH);
      w23 = fma2(t23, w23, CH);
      w01 = fma2(t01, w01, C1);
      w23 = fma2(t23, w23, C1);
      u64 u01 = mul2(t01, w01);
      u64 u23 = mul2(t23, w23);
      lacc01 = add2(lacc01, u01);
      lacc23 = add2(lacc23, u23);
      float2 f01 = unpack2(u01);
      float2 f23 = unpack2(u23);
      // ---- roundtrip P through per-warp smem to form A fragment ----
      // store: (row=gid, col=2*tig),(col+1); (row=gid+8, ...)
      uint32_t sa = pbase_a + (uint32_t)((gid*12 + 2*tig) * 4);
      sts_u32(sa,            cvt_tf32(f01.x));
      sts_u32(sa + 4,        cvt_tf32(f01.y));
      sts_u32(sa + 8*12*4,   cvt_tf32(f23.x));
      sts_u32(sa + 8*12*4+4, cvt_tf32(f23.y));
      // load A frag: a0(gid,tig) a1(gid+8,tig) a2(gid,tig+4) a3(gid+8,tig+4)
      uint32_t pa[4];
      uint32_t la = pbase_a + (uint32_t)((gid*12 + tig) * 4);
      pa[0] = lds_u32(la);
      pa[1] = lds_u32(la + 8*12*4);
      pa[2] = lds_u32(la + 16);
      pa[3] = lds_u32(la + 8*12*4 + 16);
      // ---- O += P V : per n-tile, B frag b0 = V[keyb+tig][nt*8+gid], b1 = +4 keys
      #pragma unroll
      for (int nt=0; nt<2; nt++){
        uint32_t b0 = __float_as_uint(kt[(keyb+tig  )*KSTRIDE + nt*8 + gid]);
        uint32_t b1 = __float_as_uint(kt[(keyb+tig+4)*KSTRIDE + nt*8 + gid]);
        mma_tf32(oa[nt], pa, b0, b1);
      }
    }

    if (kb < 24){
      float* dst = sK[(kb+1) & 1];
      *(float4*)&dst[key0*KSTRIDE + q40*4] = n0;
      *(float4*)&dst[key1*KSTRIDE + q40*4] = n1;
    }
    __syncthreads();
  }

  // ---- epilogue: row sums, normalize, add M0, store ----
  float2 l01 = unpack2(lacc01);
  float2 l23 = unpack2(lacc23);
  float lr0 = l01.x + l01.y;
  float lr8 = l23.x + l23.y;
  lr0 += __shfl_xor_sync(0xffffffffu, lr0, 1);
  lr0 += __shfl_xor_sync(0xffffffffu, lr0, 2);
  lr8 += __shfl_xor_sync(0xffffffffu, lr8, 1);
  lr8 += __shfl_xor_sync(0xffffffffu, lr8, 2);
  float inv0 = 1.0f / (1600.0f + lr0);
  float inv8 = 1.0f / (1600.0f + lr8);

  const float* m0p = g_m0 + (b*NHEAD + h)*16;
  float* outb = g_attn + (b*HW + qbase)*DM + h*DH;
  #pragma unroll
  for (int nt=0; nt<2; nt++){
    int d0 = nt*8 + 2*tig;
    float m0a = m0p[d0], m0b = m0p[d0+1];
    outb[(gid  )*DM + d0    ] = (oa[nt][0] + m0a) * inv0;
    outb[(gid  )*DM + d0 + 1] = (oa[nt][1] + m0b) * inv0;
    outb[(gid+8)*DM + d0    ] = (oa[nt][2] + m0a) * inv8;
    outb[(gid+8)*DM + d0 + 1] = (oa[nt][3] + m0b) * inv8;
  }
}

// ---------------- K4: img_out = attn @ W2 + b2, transposed write + GeM partials
__global__ __launch_bounds__(256) void gemm2_kernel(const float* __restrict__ W2,
                                                    const float* __restrict__ b2,
                                                    float* __restrict__ img_out){
  __shared__ float As[64][33];
  __shared__ float Ws[32][128];
  __shared__ float colsum[128];
  int tile = blockIdx.x, ct = blockIdx.y;
  int b = tile / 25, pbase = (tile % 25) * 64;
  int tid = threadIdx.x, rgrp = tid >> 5, lane = tid & 31;
  if (tid < 128) colsum[tid] = 0.f;
  float acc[8][4];
  #pragma unroll
  for (int i=0;i<8;i++){ acc[i][0]=0.f; acc[i][1]=0.f; acc[i][2]=0.f; acc[i][3]=0.f; }

  for (int kt=0; kt<4; kt++){
    __syncthreads();
    #pragma unroll
    for (int it=0; it<2; it++){
      int idx = tid + it*256;
      int k4 = idx & 7, r = idx >> 3;
      float4 v = *(const float4*)(g_attn + (tile*64 + r)*DM + kt*32 + k4*4);
      As[r][k4*4+0]=v.x; As[r][k4*4+1]=v.y; As[r][k4*4+2]=v.z; As[r][k4*4+3]=v.w;
    }
    #pragma unroll
    for (int it=0; it<4; it++){
      int idx = tid + it*256;
      int c4 = idx & 31, k = idx >> 5;
      *(float4*)&Ws[k][c4*4] = *(const float4*)(W2 + (kt*32+k)*CI + ct*128 + c4*4);
    }
    __syncthreads();
    #pragma unroll 8
    for (int k=0;k<32;k++){
      float4 w = *(float4*)&Ws[k][lane*4];
      #pragma unroll
      for (int i=0;i<8;i++){
        float a = As[rgrp*8+i][k];
        acc[i][0] = fmaf(a, w.x, acc[i][0]);
        acc[i][1] = fmaf(a, w.y, acc[i][1]);
        acc[i][2] = fmaf(a, w.z, acc[i][2]);
        acc[i][3] = fmaf(a, w.w, acc[i][3]);
      }
    }
  }
  float4 bb = *(const float4*)(b2 + ct*128 + lane*4);
  float bv[4] = {bb.x, bb.y, bb.z, bb.w};
  #pragma unroll
  for (int j=0;j<4;j++){
    float part = 0.f; float vs[8];
    #pragma unroll
    for (int i=0;i<8;i++){
      float v = acc[i][j] + bv[j];
      vs[i] = v;
      float c = fmaxf(v, 1e-6f);
      part = fmaf(c*c, c, part);
    }
    atomicAdd(&colsum[lane*4+j], part);
    int cg = ct*128 + lane*4 + j;
    float* dst = img_out + b*CI*HW + cg*HW + pbase + rgrp*8;
    *(float4*)(dst)     = make_float4(vs[0],vs[1],vs[2],vs[3]);
    *(float4*)(dst + 4) = make_float4(vs[4],vs[5],vs[6],vs[7]);
  }
  __syncthreads();
  if (tid < 128) atomicAdd(&g_imgacc[b*CI + ct*128 + tid], colsum[tid]);
}

// ---------------- K7: cloud l2norm + segmented clamp^3 sum -------------------
__global__ __launch_bounds__(256) void cloud_kernel(const float* __restrict__ cf,
                                                    const int* __restrict__ bids,
                                                    float* __restrict__ cloud_out){
  __shared__ float sseg[NB*DM];
  __shared__ float scnt[NB];
  int tid = threadIdx.x;
  for (int i=tid; i<NB*DM; i+=256) sseg[i] = 0.f;
  if (tid < NB) scnt[tid] = 0.f;
  __syncthreads();
  int w = tid >> 5, lane = tid & 31;
  int rbase = blockIdx.x*256 + w*32;
  for (int i=0;i<32;i++){
    int row = rbase + i;
    int bid = bids[row];
    float4 v = *(const float4*)(cf + row*DM + lane*4);
    float sq = v.x*v.x + v.y*v.y + v.z*v.z + v.w*v.w;
    #pragma unroll
    for (int off=16; off; off>>=1) sq += __shfl_xor_sync(0xffffffffu, sq, off);
    float inv = 1.0f / fmaxf(sqrtf(sq), 1e-12f);
    float x0=v.x*inv, x1=v.y*inv, x2=v.z*inv, x3=v.w*inv;
    *(float4*)(cloud_out + row*DM + lane*4) = make_float4(x0,x1,x2,x3);
    float c0=fmaxf(x0,1e-6f), c1=fmaxf(x1,1e-6f), c2=fmaxf(x2,1e-6f), c3=fmaxf(x3,1e-6f);
    float* sp = sseg + bid*DM + lane*4;
    atomicAdd(sp+0, c0*c0*c0);
    atomicAdd(sp+1, c1*c1*c1);
    atomicAdd(sp+2, c2*c2*c2);
    atomicAdd(sp+3, c3*c3*c3);
    if (lane == 0) atomicAdd(&scnt[bid], 1.0f);
  }
  __syncthreads();
  for (int i=tid; i<NB*DM; i+=256) atomicAdd(&g_seg[i], sseg[i]);
  if (tid < NB) atomicAdd(&g_cnt[tid], scnt[tid]);
}

// ---------------- K8: finalize GeM outputs ----------------
__global__ void finalize_kernel(float* __restrict__ image_gem, float* __restrict__ cloud_gem){
  int i = blockIdx.x*256 + threadIdx.x;
  if (i < NB*CI) image_gem[i] = cbrtf(g_imgacc[i] * (1.0f/1600.0f));
  if (i < NB*DM) cloud_gem[i] = cbrtf(g_seg[i] / fmaxf(g_cnt[i>>7], 1.0f));
}

// ---------------- launch ----------------
extern "C" void kernel_launch(void* const* d_in, const int* in_sizes, int n_in,
                              void* d_out, int out_size){
  const float* img  = (const float*)d_in[0];
  const float* cf   = (const float*)d_in[1];
  const int*   bids = (const int*)  d_in[2];
  const float* W1   = (const float*)d_in[3];
  const float* b1   = (const float*)d_in[4];
  const float* W2   = (const float*)d_in[5];
  const float* b2   = (const float*)d_in[6];

  float* out       = (float*)d_out;
  float* img_out   = out;                                  // 8*256*1600
  float* cloud_out = out + (size_t)NB*CI*HW;               // 32768*128
  float* image_gem = cloud_out + (size_t)NCLOUD*DM;        // 2048
  float* cloud_gem = image_gem + NB*CI;                    // 1024

  zero_kernel<<<8, 256>>>();
  gemm1_kernel<<<200, 256>>>(img, W1, b1);
  m0_kernel<<<NB*NHEAD, 128>>>();
  attn_mma_kernel<<<dim3(25, NHEAD, NB), 128>>>();
  gemm2_kernel<<<dim3(200, 2), 256>>>(W2, b2, img_out);
  cloud_kernel<<<NCLOUD/256, 256>>>(cf, bids, cloud_out);
  finalize_kernel<<<8, 256>>>(image_gem, cloud_gem);
}

// round 4
// speedup vs baseline: 1.7140x; 1.0043x over previous
#include <cuda_runtime.h>
#include <cstdint>

// ---------------- constants ----------------
#define NB      8
#define CI      256
#define HW      1600
#define DM      128
#define NHEAD   8
#define DH      16
#define NROWS   (NB*HW)        // 12800
#define NCLOUD  32768

// ---------------- device scratch ----------------
__device__ float g_tok [NROWS*DM];     // l2-normalized image tokens
__device__ float g_attn[NROWS*DM];     // attention output
__device__ float g_m0  [NB*NHEAD*DH];  // per (b,h) sum of v over keys
__device__ float g_imgacc[NB*CI];
__device__ float g_seg  [NB*DM];
__device__ float g_cnt  [NB];

typedef unsigned long long u64;

// ---------------- packed f32x2 helpers ----------------
__device__ __forceinline__ u64 fma2(u64 a, u64 b, u64 c){
  u64 d; asm("fma.rn.f32x2 %0, %1, %2, %3;" : "=l"(d) : "l"(a), "l"(b), "l"(c)); return d;
}
__device__ __forceinline__ u64 mul2(u64 a, u64 b){
  u64 d; asm("mul.rn.f32x2 %0, %1, %2;" : "=l"(d) : "l"(a), "l"(b)); return d;
}
__device__ __forceinline__ u64 add2(u64 a, u64 b){
  u64 d; asm("add.rn.f32x2 %0, %1, %2;" : "=l"(d) : "l"(a), "l"(b)); return d;
}
__device__ __forceinline__ u64 pack2(float x, float y){
  u64 d; asm("mov.b64 %0, {%1, %2};" : "=l"(d) : "f"(x), "f"(y)); return d;
}
__device__ __forceinline__ float2 unpack2(u64 u){
  float2 f; asm("mov.b64 {%0, %1}, %2;" : "=f"(f.x), "=f"(f.y) : "l"(u)); return f;
}

// ---------------- tf32 mma helpers ----------------
__device__ __forceinline__ uint32_t cvt_tf32(float f){
  uint32_t r; asm("cvt.rna.tf32.f32 %0, %1;" : "=r"(r) : "f"(f)); return r;
}
__device__ __forceinline__ void mma_tf32(float* c, const uint32_t* a, uint32_t b0, uint32_t b1){
  asm volatile("mma.sync.aligned.m16n8k8.row.col.f32.tf32.tf32.f32 "
      "{%0,%1,%2,%3}, {%4,%5,%6,%7}, {%8,%9}, {%0,%1,%2,%3};"
      : "+f"(c[0]), "+f"(c[1]), "+f"(c[2]), "+f"(c[3])
      : "r"(a[0]), "r"(a[1]), "r"(a[2]), "r"(a[3]), "r"(b0), "r"(b1));
}
__device__ __forceinline__ void sts_u32(uint32_t addr, uint32_t v){
  asm volatile("st.shared.b32 [%0], %1;" :: "r"(addr), "r"(v));
}
__device__ __forceinline__ uint32_t lds_u32(uint32_t addr){
  uint32_t v; asm volatile("ld.shared.b32 %0, [%1];" : "=r"(v) : "r"(addr)); return v;
}

// ---------------- K0: zero accumulators ----------------
__global__ void zero_kernel(){
  int i = blockIdx.x*256 + threadIdx.x;
  if (i < NB*CI) g_imgacc[i] = 0.f;
  if (i < NB*DM) g_seg[i]    = 0.f;
  if (i < NB)    g_cnt[i]    = 0.f;
}

// ---------------- K1: x = einsum(bchw,cd)+b1, rowwise l2norm -> g_tok --------
__global__ __launch_bounds__(256) void gemm1_kernel(const float* __restrict__ img,
                                                    const float* __restrict__ W1,
                                                    const float* __restrict__ b1){
  __shared__ float As[32][64];
  __shared__ float Ws[32][128];
  int tile = blockIdx.x;
  int b = tile / 25;
  int pbase = (tile % 25) * 64;
  const float* Ab = img + b*CI*HW + pbase;
  int tid = threadIdx.x;
  int rgrp = tid >> 5, lane = tid & 31;
  float acc[8][4];
  #pragma unroll
  for (int i=0;i<8;i++){ acc[i][0]=0.f; acc[i][1]=0.f; acc[i][2]=0.f; acc[i][3]=0.f; }

  for (int kt=0; kt<8; kt++){
    __syncthreads();
    #pragma unroll
    for (int it=0; it<8; it++){
      int idx = tid + it*256;
      int r = idx & 63, k = idx >> 6;
      As[k][r] = Ab[(kt*32+k)*HW + r];
    }
    #pragma unroll
    for (int it=0; it<4; it++){
      int idx = tid + it*256;
      int c4 = idx & 31, k = idx >> 5;
      *(float4*)&Ws[k][c4*4] = *(const float4*)(W1 + (kt*32+k)*DM + c4*4);
    }
    __syncthreads();
    #pragma unroll 8
    for (int k=0;k<32;k++){
      float4 w  = *(float4*)&Ws[k][lane*4];
      float4 a0 = *(float4*)&As[k][rgrp*8];
      float4 a1 = *(float4*)&As[k][rgrp*8+4];
      float a[8] = {a0.x,a0.y,a0.z,a0.w,a1.x,a1.y,a1.z,a1.w};
      #pragma unroll
      for (int i=0;i<8;i++){
        acc[i][0] = fmaf(a[i], w.x, acc[i][0]);
        acc[i][1] = fmaf(a[i], w.y, acc[i][1]);
        acc[i][2] = fmaf(a[i], w.z, acc[i][2]);
        acc[i][3] = fmaf(a[i], w.w, acc[i][3]);
      }
    }
  }
  float4 bb = *(const float4*)(b1 + lane*4);
  int Rbase = tile*64 + rgrp*8;
  #pragma unroll
  for (int i=0;i<8;i++){
    float x0 = acc[i][0]+bb.x, x1 = acc[i][1]+bb.y, x2 = acc[i][2]+bb.z, x3 = acc[i][3]+bb.w;
    float sq = x0*x0 + x1*x1 + x2*x2 + x3*x3;
    #pragma unroll
    for (int off=16; off; off>>=1) sq += __shfl_xor_sync(0xffffffffu, sq, off);
    float inv = 1.0f / fmaxf(sqrtf(sq), 1e-12f);
    *(float4*)(g_tok + (Rbase+i)*DM + lane*4) = make_float4(x0*inv, x1*inv, x2*inv, x3*inv);
  }
}

// ---------------- K2: M0[b,h,d] = sum over keys of v ----------------
__global__ __launch_bounds__(128) void m0_kernel(){
  int bh = blockIdx.x;                  // 64 blocks
  const float* base = g_tok + (bh>>3)*HW*DM + (bh&7)*DH;
  __shared__ float red[128];
  int tid = threadIdx.x;
  int d = tid & 15, seg = tid >> 4;     // 8 segments
  float s = 0.f;
  for (int t = seg; t < HW; t += 8) s += base[t*DM + d];
  red[tid] = s;
  __syncthreads();
  if (tid < 16){
    float a = 0.f;
    #pragma unroll
    for (int i=0;i<8;i++) a += red[tid + i*16];
    g_m0[bh*16 + tid] = a;
  }
}

// ---------------- K3: attention via tf32 mma.sync ----------------
// warp = 16 queries, CTA = 64 queries; grid (25, NHEAD, NB). exact tiling.
// S = (Q/4)K^T (mma), u = expm1(S) deg-5 poly, O = M0 + U*V (mma), l = 1600 + sum u.
#define KSTRIDE 20
__global__ __launch_bounds__(128) void attn_mma_kernel(){
  __shared__ float sK[2][64*KSTRIDE];          // key tile, stride-20 padded
  __shared__ uint32_t sP[4][16*12];            // per-warp P roundtrip (tf32 bits)
  int b = blockIdx.z, h = blockIdx.y;
  int tid = threadIdx.x, w = tid >> 5, lane = tid & 31;
  int gid = lane >> 2, tig = lane & 3;
  const float* base = g_tok + b*HW*DM + h*DH;  // token t, dim d at base[t*DM + d]
  int qbase = blockIdx.x*64 + w*16;

  // Q fragments (scaled by 0.25, rna-converted). a0:(gid,tig) a1:(gid+8,tig) a2:(gid,tig+4) a3:(gid+8,tig+4)
  uint32_t qa[2][4];
  #pragma unroll
  for (int kc=0; kc<2; kc++){
    qa[kc][0] = cvt_tf32(base[(qbase+gid  )*DM + kc*8 + tig    ] * 0.25f);
    qa[kc][1] = cvt_tf32(base[(qbase+gid+8)*DM + kc*8 + tig    ] * 0.25f);
    qa[kc][2] = cvt_tf32(base[(qbase+gid  )*DM + kc*8 + tig + 4] * 0.25f);
    qa[kc][3] = cvt_tf32(base[(qbase+gid+8)*DM + kc*8 + tig + 4] * 0.25f);
  }

  float oa[2][4];
  #pragma unroll
  for (int nt=0; nt<2; nt++){ oa[nt][0]=0.f; oa[nt][1]=0.f; oa[nt][2]=0.f; oa[nt][3]=0.f; }
  u64 lacc01 = 0ULL, lacc23 = 0ULL;

  const u64 C120 = pack2(8.3333333e-3f, 8.3333333e-3f);   // 1/120
  const u64 C24  = pack2(4.1666667e-2f, 4.1666667e-2f);   // 1/24
  const u64 C6   = pack2(1.6666667e-1f, 1.6666667e-1f);   // 1/6
  const u64 CH   = pack2(0.5f, 0.5f);
  const u64 C1   = pack2(1.0f, 1.0f);

  // K tile loading: 256 float4s per tile, 2 per thread
  int key0 = tid >> 2, q40 = tid & 3;          // first half: keys 0..31
  int key1 = key0 + 32;                        // second half: keys 32..63
  uint32_t pbase_a;
  {
    uint32_t* pp = &sP[w][0];
    pbase_a = (uint32_t)__cvta_generic_to_shared(pp);
  }

  // prologue: tile 0
  {
    float4 v0 = *(const float4*)(base + (key0)*DM + q40*4);
    float4 v1 = *(const float4*)(base + (key1)*DM + q40*4);
    *(float4*)&sK[0][key0*KSTRIDE + q40*4] = v0;
    *(float4*)&sK[0][key1*KSTRIDE + q40*4] = v1;
  }
  __syncthreads();

  for (int kb=0; kb<25; kb++){
    float4 n0, n1;
    if (kb < 24){
      n0 = *(const float4*)(base + ((kb+1)*64 + key0)*DM + q40*4);
      n1 = *(const float4*)(base + ((kb+1)*64 + key1)*DM + q40*4);
    }
    const float* kt = sK[kb & 1];

    #pragma unroll
    for (int ck=0; ck<8; ck++){
      int keyb = ck*8;
      // ---- scores S = Q K^T ----
      float c[4] = {0.f, 0.f, 0.f, 0.f};
      {
        // B frag (k-chunk kc): b0 = K[keyb+gid][kc*8+tig], b1 = +4 dims
        uint32_t b0 = __float_as_uint(kt[(keyb+gid)*KSTRIDE + tig    ]);
        uint32_t b1 = __float_as_uint(kt[(keyb+gid)*KSTRIDE + tig + 4]);
        mma_tf32(c, qa[0], b0, b1);
        uint32_t b2 = __float_as_uint(kt[(keyb+gid)*KSTRIDE + 8 + tig    ]);
        uint32_t b3 = __float_as_uint(kt[(keyb+gid)*KSTRIDE + 8 + tig + 4]);
        mma_tf32(c, qa[1], b2, b3);
      }
      // ---- u = expm1(t), deg-5, packed ----
      u64 t01 = pack2(c[0], c[1]);
      u64 t23 = pack2(c[2], c[3]);
      u64 w01 = fma2(t01, C120, C24);
      u64 w23 = fma2(t23, C120, C24);
      w01 = fma2(t01, w01, C6);
      w23 = fma2(t23, w23, C6);
      w01 = fma2(t01, w01, CH);
      w23 = fma2(t23, w23, CH);
      w01 = fma2(t01, w01, C1);
      w23 = fma2(t23, w23, C1);
      u64 u01 = mul2(t01, w01);
      u64 u23 = mul2(t23, w23);
      lacc01 = add2(lacc01, u01);
      lacc23 = add2(lacc23, u23);
      float2 f01 = unpack2(u01);
      float2 f23 = unpack2(u23);
      // ---- roundtrip P through per-warp smem to form A fragment ----
      // store: (row=gid, col=2*tig),(col+1); (row=gid+8, ...)
      uint32_t sa = pbase_a + (uint32_t)((gid*12 + 2*tig) * 4);
      sts_u32(sa,            cvt_tf32(f01.x));
      sts_u32(sa + 4,        cvt_tf32(f01.y));
      sts_u32(sa + 8*12*4,   cvt_tf32(f23.x));
      sts_u32(sa + 8*12*4+4, cvt_tf32(f23.y));
      // load A frag: a0(gid,tig) a1(gid+8,tig) a2(gid,tig+4) a3(gid+8,tig+4)
      uint32_t pa[4];
      uint32_t la = pbase_a + (uint32_t)((gid*12 + tig) * 4);
      pa[0] = lds_u32(la);
      pa[1] = lds_u32(la + 8*12*4);
      pa[2] = lds_u32(la + 16);
      pa[3] = lds_u32(la + 8*12*4 + 16);
      // ---- O += P V : per n-tile, B frag b0 = V[keyb+tig][nt*8+gid], b1 = +4 keys
      #pragma unroll
      for (int nt=0; nt<2; nt++){
        uint32_t b0 = __float_as_uint(kt[(keyb+tig  )*KSTRIDE + nt*8 + gid]);
        uint32_t b1 = __float_as_uint(kt[(keyb+tig+4)*KSTRIDE + nt*8 + gid]);
        mma_tf32(oa[nt], pa, b0, b1);
      }
    }

    if (kb < 24){
      float* dst = sK[(kb+1) & 1];
      *(float4*)&dst[key0*KSTRIDE + q40*4] = n0;
      *(float4*)&dst[key1*KSTRIDE + q40*4] = n1;
    }
    __syncthreads();
  }

  // ---- epilogue: row sums, normalize, add M0, store ----
  float2 l01 = unpack2(lacc01);
  float2 l23 = unpack2(lacc23);
  float lr0 = l01.x + l01.y;
  float lr8 = l23.x + l23.y;
  lr0 += __shfl_xor_sync(0xffffffffu, lr0, 1);
  lr0 += __shfl_xor_sync(0xffffffffu, lr0, 2);
  lr8 += __shfl_xor_sync(0xffffffffu, lr8, 1);
  lr8 += __shfl_xor_sync(0xffffffffu, lr8, 2);
  float inv0 = 1.0f / (1600.0f + lr0);
  float inv8 = 1.0f / (1600.0f + lr8);

  const float* m0p = g_m0 + (b*NHEAD + h)*16;
  float* outb = g_attn + (b*HW + qbase)*DM + h*DH;
  #pragma unroll
  for (int nt=0; nt<2; nt++){
    int d0 = nt*8 + 2*tig;
    float m0a = m0p[d0], m0b = m0p[d0+1];
    outb[(gid  )*DM + d0    ] = (oa[nt][0] + m0a) * inv0;
    outb[(gid  )*DM + d0 + 1] = (oa[nt][1] + m0b) * inv0;
    outb[(gid+8)*DM + d0    ] = (oa[nt][2] + m0a) * inv8;
    outb[(gid+8)*DM + d0 + 1] = (oa[nt][3] + m0b) * inv8;
  }
}

// ---------------- K4: img_out = attn @ W2 + b2, transposed write + GeM partials
__global__ __launch_bounds__(256) void gemm2_kernel(const float* __restrict__ W2,
                                                    const float* __restrict__ b2,
                                                    float* __restrict__ img_out){
  __shared__ float As[64][33];
  __shared__ float Ws[32][128];
  __shared__ float colsum[128];
  int tile = blockIdx.x, ct = blockIdx.y;
  int b = tile / 25, pbase = (tile % 25) * 64;
  int tid = threadIdx.x, rgrp = tid >> 5, lane = tid & 31;
  if (tid < 128) colsum[tid] = 0.f;
  float acc[8][4];
  #pragma unroll
  for (int i=0;i<8;i++){ acc[i][0]=0.f; acc[i][1]=0.f; acc[i][2]=0.f; acc[i][3]=0.f; }

  for (int kt=0; kt<4; kt++){
    __syncthreads();
    #pragma unroll
    for (int it=0; it<2; it++){
      int idx = tid + it*256;
      int k4 = idx & 7, r = idx >> 3;
      float4 v = *(const float4*)(g_attn + (tile*64 + r)*DM + kt*32 + k4*4);
      As[r][k4*4+0]=v.x; As[r][k4*4+1]=v.y; As[r][k4*4+2]=v.z; As[r][k4*4+3]=v.w;
    }
    #pragma unroll
    for (int it=0; it<4; it++){
      int idx = tid + it*256;
      int c4 = idx & 31, k = idx >> 5;
      *(float4*)&Ws[k][c4*4] = *(const float4*)(W2 + (kt*32+k)*CI + ct*128 + c4*4);
    }
    __syncthreads();
    #pragma unroll 8
    for (int k=0;k<32;k++){
      float4 w = *(float4*)&Ws[k][lane*4];
      #pragma unroll
      for (int i=0;i<8;i++){
        float a = As[rgrp*8+i][k];
        acc[i][0] = fmaf(a, w.x, acc[i][0]);
        acc[i][1] = fmaf(a, w.y, acc[i][1]);
        acc[i][2] = fmaf(a, w.z, acc[i][2]);
        acc[i][3] = fmaf(a, w.w, acc[i][3]);
      }
    }
  }
  float4 bb = *(const float4*)(b2 + ct*128 + lane*4);
  float bv[4] = {bb.x, bb.y, bb.z, bb.w};
  #pragma unroll
  for (int j=0;j<4;j++){
    float part = 0.f; float vs[8];
    #pragma unroll
    for (int i=0;i<8;i++){
      float v = acc[i][j] + bv[j];
      vs[i] = v;
      float c = fmaxf(v, 1e-6f);
      part = fmaf(c*c, c, part);
    }
    atomicAdd(&colsum[lane*4+j], part);
    int cg = ct*128 + lane*4 + j;
    float* dst = img_out + b*CI*HW + cg*HW + pbase + rgrp*8;
    *(float4*)(dst)     = make_float4(vs[0],vs[1],vs[2],vs[3]);
    *(float4*)(dst + 4) = make_float4(vs[4],vs[5],vs[6],vs[7]);
  }
  __syncthreads();
  if (tid < 128) atomicAdd(&g_imgacc[b*CI + ct*128 + tid], colsum[tid]);
}

// ---------------- K7: cloud l2norm + segmented clamp^3 sum -------------------
__global__ __launch_bounds__(256) void cloud_kernel(const float* __restrict__ cf,
                                                    const int* __restrict__ bids,
                                                    float* __restrict__ cloud_out){
  __shared__ float sseg[NB*DM];
  __shared__ float scnt[NB];
  int tid = threadIdx.x;
  for (int i=tid; i<NB*DM; i+=256) sseg[i] = 0.f;
  if (tid < NB) scnt[tid] = 0.f;
  __syncthreads();
  int w = tid >> 5, lane = tid & 31;
  int rbase = blockIdx.x*256 + w*32;
  for (int i=0;i<32;i++){
    int row = rbase + i;
    int bid = bids[row];
    float4 v = *(const float4*)(cf + row*DM + lane*4);
    float sq = v.x*v.x + v.y*v.y + v.z*v.z + v.w*v.w;
    #pragma unroll
    for (int off=16; off; off>>=1) sq += __shfl_xor_sync(0xffffffffu, sq, off);
    float inv = 1.0f / fmaxf(sqrtf(sq), 1e-12f);
    float x0=v.x*inv, x1=v.y*inv, x2=v.z*inv, x3=v.w*inv;
    *(float4*)(cloud_out + row*DM + lane*4) = make_float4(x0,x1,x2,x3);
    float c0=fmaxf(x0,1e-6f), c1=fmaxf(x1,1e-6f), c2=fmaxf(x2,1e-6f), c3=fmaxf(x3,1e-6f);
    float* sp = sseg + bid*DM + lane*4;
    atomicAdd(sp+0, c0*c0*c0);
    atomicAdd(sp+1, c1*c1*c1);
    atomicAdd(sp+2, c2*c2*c2);
    atomicAdd(sp+3, c3*c3*c3);
    if (lane == 0) atomicAdd(&scnt[bid], 1.0f);
  }
  __syncthreads();
  for (int i=tid; i<NB*DM; i+=256) atomicAdd(&g_seg[i], sseg[i]);
  if (tid < NB) atomicAdd(&g_cnt[tid], scnt[tid]);
}

// ---------------- K8: finalize GeM outputs ----------------
__global__ void finalize_kernel(float* __restrict__ image_gem, float* __restrict__ cloud_gem){
  int i = blockIdx.x*256 + threadIdx.x;
  if (i < NB*CI) image_gem[i] = cbrtf(g_imgacc[i] * (1.0f/1600.0f));
  if (i < NB*DM) cloud_gem[i] = cbrtf(g_seg[i] / fmaxf(g_cnt[i>>7], 1.0f));
}

// ---------------- launch ----------------
extern "C" void kernel_launch(void* const* d_in, const int* in_sizes, int n_in,
                              void* d_out, int out_size){
  const float* img  = (const float*)d_in[0];
  const float* cf   = (const float*)d_in[1];
  const int*   bids = (const int*)  d_in[2];
  const float* W1   = (const float*)d_in[3];
  const float* b1   = (const float*)d_in[4];
  const float* W2   = (const float*)d_in[5];
  const float* b2   = (const float*)d_in[6];

  float* out       = (float*)d_out;
  float* img_out   = out;                                  // 8*256*1600
  float* cloud_out = out + (size_t)NB*CI*HW;               // 32768*128
  float* image_gem = cloud_out + (size_t)NCLOUD*DM;        // 2048
  float* cloud_gem = image_gem + NB*CI;                    // 1024

  zero_kernel<<<8, 256>>>();
  gemm1_kernel<<<200, 256>>>(img, W1, b1);
  m0_kernel<<<NB*NHEAD, 128>>>();
  attn_mma_kernel<<<dim3(25, NHEAD, NB), 128>>>();
  gemm2_kernel<<<dim3(200, 2), 256>>>(W2, b2, img_out);
  cloud_kernel<<<NCLOUD/256, 256>>>(cf, bids, cloud_out);
  finalize_kernel<<<8, 256>>>(image_gem, cloud_gem);
}

// round 5
// speedup vs baseline: 2.3460x; 1.3687x over previous
#include <cuda_runtime.h>
#include <cuda_bf16.h>
#include <cstdint>

// ---------------- constants ----------------
#define NB      8
#define CI      256
#define HW      1600
#define DM      128
#define NHEAD   8
#define DH      16
#define NROWS   (NB*HW)        // 12800
#define NCLOUD  32768

// ---------------- device scratch ----------------
__device__ float g_tok [NROWS*DM];     // l2-normalized image tokens
__device__ float g_attn[NROWS*DM];     // attention output
__device__ float g_m0  [NB*NHEAD*DH];  // per (b,h) sum of v over keys
__device__ float g_imgacc[NB*CI];
__device__ float g_seg  [NB*DM];
__device__ float g_cnt  [NB];

typedef unsigned long long u64;

// ---------------- packed f32x2 helpers ----------------
__device__ __forceinline__ u64 fma2(u64 a, u64 b, u64 c){
  u64 d; asm("fma.rn.f32x2 %0, %1, %2, %3;" : "=l"(d) : "l"(a), "l"(b), "l"(c)); return d;
}
__device__ __forceinline__ u64 mul2(u64 a, u64 b){
  u64 d; asm("mul.rn.f32x2 %0, %1, %2;" : "=l"(d) : "l"(a), "l"(b)); return d;
}
__device__ __forceinline__ u64 add2(u64 a, u64 b){
  u64 d; asm("add.rn.f32x2 %0, %1, %2;" : "=l"(d) : "l"(a), "l"(b)); return d;
}
__device__ __forceinline__ u64 pack2(float x, float y){
  u64 d; asm("mov.b64 %0, {%1, %2};" : "=l"(d) : "f"(x), "f"(y)); return d;
}
__device__ __forceinline__ float2 unpack2(u64 u){
  float2 f; asm("mov.b64 {%0, %1}, %2;" : "=f"(f.x), "=f"(f.y) : "l"(u)); return f;
}

// bf16x2 pack: lower = a, upper = b
__device__ __forceinline__ uint32_t cvt_bf16x2(u64 p){
  float2 f = unpack2(p);
  uint32_t r;
  asm("cvt.rn.bf16x2.f32 %0, %1, %2;" : "=r"(r) : "f"(f.y), "f"(f.x));
  return r;
}
__device__ __forceinline__ uint32_t packbf(__nv_bfloat16 a, __nv_bfloat16 b){
  __nv_bfloat162 t(a, b);
  return *reinterpret_cast<uint32_t*>(&t);
}

// ---------------- mma / ldmatrix helpers ----------------
__device__ __forceinline__ void mma_bf16(float* c, const uint32_t* a, uint32_t b0, uint32_t b1){
  asm volatile("mma.sync.aligned.m16n8k16.row.col.f32.bf16.bf16.f32 "
      "{%0,%1,%2,%3}, {%4,%5,%6,%7}, {%8,%9}, {%0,%1,%2,%3};"
      : "+f"(c[0]), "+f"(c[1]), "+f"(c[2]), "+f"(c[3])
      : "r"(a[0]), "r"(a[1]), "r"(a[2]), "r"(a[3]), "r"(b0), "r"(b1));
}
__device__ __forceinline__ void ldsm4(uint32_t addr, uint32_t* r){
  asm volatile("ldmatrix.sync.aligned.m8n8.x4.shared.b16 {%0,%1,%2,%3}, [%4];"
      : "=r"(r[0]), "=r"(r[1]), "=r"(r[2]), "=r"(r[3]) : "r"(addr));
}
__device__ __forceinline__ void ldsm4t(uint32_t addr, uint32_t* r){
  asm volatile("ldmatrix.sync.aligned.m8n8.x4.trans.shared.b16 {%0,%1,%2,%3}, [%4];"
      : "=r"(r[0]), "=r"(r[1]), "=r"(r[2]), "=r"(r[3]) : "r"(addr));
}
__device__ __forceinline__ void sts128(uint32_t addr, uint32_t r0, uint32_t r1, uint32_t r2, uint32_t r3){
  asm volatile("st.shared.v4.b32 [%0], {%1,%2,%3,%4};"
      :: "r"(addr), "r"(r0), "r"(r1), "r"(r2), "r"(r3));
}

// split 8 floats into hi/lo bf16 and store as two 16B rows
__device__ __forceinline__ void split_store(uint32_t dstKh, uint32_t dstKl, float4 a, float4 b){
  float x[8] = {a.x, a.y, a.z, a.w, b.x, b.y, b.z, b.w};
  uint32_t hi[4], lo[4];
  #pragma unroll
  for (int i=0;i<4;i++){
    float x0 = x[2*i], x1 = x[2*i+1];
    __nv_bfloat16 h0 = __float2bfloat16_rn(x0);
    __nv_bfloat16 h1 = __float2bfloat16_rn(x1);
    float r0 = x0 - __bfloat162float(h0);
    float r1 = x1 - __bfloat162float(h1);
    __nv_bfloat16 l0 = __float2bfloat16_rn(r0);
    __nv_bfloat16 l1 = __float2bfloat16_rn(r1);
    hi[i] = packbf(h0, h1);
    lo[i] = packbf(l0, l1);
  }
  sts128(dstKh, hi[0], hi[1], hi[2], hi[3]);
  sts128(dstKl, lo[0], lo[1], lo[2], lo[3]);
}

// ---------------- K0: zero accumulators ----------------
__global__ void zero_kernel(){
  int i = blockIdx.x*256 + threadIdx.x;
  if (i < NB*CI) g_imgacc[i] = 0.f;
  if (i < NB*DM) g_seg[i]    = 0.f;
  if (i < NB)    g_cnt[i]    = 0.f;
}

// ---------------- K1: x = einsum(bchw,cd)+b1, rowwise l2norm -> g_tok --------
__global__ __launch_bounds__(256) void gemm1_kernel(const float* __restrict__ img,
                                                    const float* __restrict__ W1,
                                                    const float* __restrict__ b1){
  __shared__ float As[32][64];
  __shared__ float Ws[32][128];
  int tile = blockIdx.x;
  int b = tile / 25;
  int pbase = (tile % 25) * 64;
  const float* Ab = img + b*CI*HW + pbase;
  int tid = threadIdx.x;
  int rgrp = tid >> 5, lane = tid & 31;
  float acc[8][4];
  #pragma unroll
  for (int i=0;i<8;i++){ acc[i][0]=0.f; acc[i][1]=0.f; acc[i][2]=0.f; acc[i][3]=0.f; }

  for (int kt=0; kt<8; kt++){
    __syncthreads();
    #pragma unroll
    for (int it=0; it<8; it++){
      int idx = tid + it*256;
      int r = idx & 63, k = idx >> 6;
      As[k][r] = Ab[(kt*32+k)*HW + r];
    }
    #pragma unroll
    for (int it=0; it<4; it++){
      int idx = tid + it*256;
      int c4 = idx & 31, k = idx >> 5;
      *(float4*)&Ws[k][c4*4] = *(const float4*)(W1 + (kt*32+k)*DM + c4*4);
    }
    __syncthreads();
    #pragma unroll 8
    for (int k=0;k<32;k++){
      float4 w  = *(float4*)&Ws[k][lane*4];
      float4 a0 = *(float4*)&As[k][rgrp*8];
      float4 a1 = *(float4*)&As[k][rgrp*8+4];
      float a[8] = {a0.x,a0.y,a0.z,a0.w,a1.x,a1.y,a1.z,a1.w};
      #pragma unroll
      for (int i=0;i<8;i++){
        acc[i][0] = fmaf(a[i], w.x, acc[i][0]);
        acc[i][1] = fmaf(a[i], w.y, acc[i][1]);
        acc[i][2] = fmaf(a[i], w.z, acc[i][2]);
        acc[i][3] = fmaf(a[i], w.w, acc[i][3]);
      }
    }
  }
  float4 bb = *(const float4*)(b1 + lane*4);
  int Rbase = tile*64 + rgrp*8;
  #pragma unroll
  for (int i=0;i<8;i++){
    float x0 = acc[i][0]+bb.x, x1 = acc[i][1]+bb.y, x2 = acc[i][2]+bb.z, x3 = acc[i][3]+bb.w;
    float sq = x0*x0 + x1*x1 + x2*x2 + x3*x3;
    #pragma unroll
    for (int off=16; off; off>>=1) sq += __shfl_xor_sync(0xffffffffu, sq, off);
    float inv = 1.0f / fmaxf(sqrtf(sq), 1e-12f);
    *(float4*)(g_tok + (Rbase+i)*DM + lane*4) = make_float4(x0*inv, x1*inv, x2*inv, x3*inv);
  }
}

// ---------------- K2: M0[b,h,d] = sum over keys of v ----------------
__global__ __launch_bounds__(128) void m0_kernel(){
  int bh = blockIdx.x;
  const float* base = g_tok + (bh>>3)*HW*DM + (bh&7)*DH;
  __shared__ float red[128];
  int tid = threadIdx.x;
  int d = tid & 15, seg = tid >> 4;
  float s = 0.f;
  for (int t = seg; t < HW; t += 8) s += base[t*DM + d];
  red[tid] = s;
  __syncthreads();
  if (tid < 16){
    float a = 0.f;
    #pragma unroll
    for (int i=0;i<8;i++) a += red[tid + i*16];
    g_m0[bh*16 + tid] = a;
  }
}

// ---------------- K3: attention via split-bf16 mma, FA register chaining ------
// scores S = qh*kh + qh*kl + ql*kh (3 mmas, k=16); u = expm1(S); P->bf16 in regs
// feeds PV mma directly (C layout == A layout for m16n8k16). O = M0 + U*V.
// smem: per buffer 4 planes (KhA,KhB,KlA,KlB), each [64 keys][8 bf16] rows of 16B.
__global__ __launch_bounds__(128) void attn_bf16_kernel(){
  __shared__ __align__(1024) unsigned char sbuf[2][4096];
  int b = blockIdx.z, h = blockIdx.y;
  int tid = threadIdx.x, w = tid >> 5, lane = tid & 31;
  int gid = lane >> 2, tig = lane & 3;
  const float* base = g_tok + b*HW*DM + h*DH;
  int qbase = blockIdx.x*64 + w*16;

  // ---- Q fragments, scaled by 0.25 (exact), split hi/lo ----
  uint32_t qh[4], ql[4];
  #pragma unroll
  for (int i=0;i<4;i++){
    int row = qbase + gid + (i & 1)*8;
    int col = 2*tig + (i >> 1)*8;
    float2 v = *(const float2*)(base + row*DM + col);
    float x0 = v.x*0.25f, x1 = v.y*0.25f;
    __nv_bfloat16 h0 = __float2bfloat16_rn(x0);
    __nv_bfloat16 h1 = __float2bfloat16_rn(x1);
    float r0 = x0 - __bfloat162float(h0);
    float r1 = x1 - __bfloat162float(h1);
    qh[i] = packbf(h0, h1);
    ql[i] = packbf(__float2bfloat16_rn(r0), __float2bfloat16_rn(r1));
  }

  float oa0[4] = {0.f,0.f,0.f,0.f};
  float oa1[4] = {0.f,0.f,0.f,0.f};
  u64 lA01 = 0ULL, lA23 = 0ULL, lB01 = 0ULL, lB23 = 0ULL;

  const u64 C120 = pack2(8.3333333e-3f, 8.3333333e-3f);
  const u64 C24  = pack2(4.1666667e-2f, 4.1666667e-2f);
  const u64 C6   = pack2(1.6666667e-1f, 1.6666667e-1f);
  const u64 CH   = pack2(0.5f, 0.5f);
  const u64 C1   = pack2(1.0f, 1.0f);

  // ---- ldmatrix per-lane base addresses ----
  uint32_t sb0 = (uint32_t)__cvta_generic_to_shared(&sbuf[0][0]);
  int r7 = lane & 7;
  // score Kh: m0/m1 = keys kb..+7 planes A/B (b0,b1 chunkA); m2/m3 = keys +8 (chunkB)
  uint32_t aScore = sb0 + (uint32_t)((r7 + ((lane >> 4) & 1)*8)*16 + ((lane >> 3) & 1)*1024);
  // PV (trans): m0 = plane A keys kb..+7, m1 = plane A keys +8, m2/m3 = plane B
  uint32_t aPV    = sb0 + (uint32_t)((r7 + ((lane >> 3) & 1)*8)*16 + ((lane >> 4) & 1)*1024);

  // ---- tile store addressing ----
  int key = tid >> 1, halfd = tid & 1;
  const float* gsrc = base + key*DM + halfd*8;
  uint32_t dstKh = sb0 + (uint32_t)(halfd*1024 + key*16);

  // prologue: tile 0 -> buffer 0
  {
    float4 a0 = *(const float4*)(gsrc);
    float4 a1 = *(const float4*)(gsrc + 4);
    split_store(dstKh, dstKh + 2048, a0, a1);
  }
  __syncthreads();

  for (int kb=0; kb<25; kb++){
    float4 n0, n1;
    if (kb < 24){
      n0 = *(const float4*)(gsrc + (kb+1)*64*DM);
      n1 = *(const float4*)(gsrc + (kb+1)*64*DM + 4);
    }
    uint32_t bufoff = (uint32_t)((kb & 1)*4096);
    uint32_t aS = aScore + bufoff;
    uint32_t aP = aPV + bufoff;

    #pragma unroll
    for (int ck=0; ck<4; ck++){
      uint32_t off = (uint32_t)(ck*256);
      uint32_t kh[4], kl[4], vv[4];
      ldsm4 (aS + off,        kh);
      ldsm4 (aS + 2048 + off, kl);
      ldsm4t(aP + off,        vv);

      float cA[4] = {0.f,0.f,0.f,0.f};
      float cB[4] = {0.f,0.f,0.f,0.f};
      mma_bf16(cA, qh, kh[0], kh[1]);
      mma_bf16(cA, qh, kl[0], kl[1]);
      mma_bf16(cA, ql, kh[0], kh[1]);
      mma_bf16(cB, qh, kh[2], kh[3]);
      mma_bf16(cB, qh, kl[2], kl[3]);
      mma_bf16(cB, ql, kh[2], kh[3]);

      // u = expm1(t), deg-5, packed pairs
      u64 tA01 = pack2(cA[0], cA[1]);
      u64 tA23 = pack2(cA[2], cA[3]);
      u64 tB01 = pack2(cB[0], cB[1]);
      u64 tB23 = pack2(cB[2], cB[3]);
      u64 wA01 = fma2(tA01, C120, C24);
      u64 wA23 = fma2(tA23, C120, C24);
      u64 wB01 = fma2(tB01, C120, C24);
      u64 wB23 = fma2(tB23, C120, C24);
      wA01 = fma2(tA01, wA01, C6);  wA23 = fma2(tA23, wA23, C6);
      wB01 = fma2(tB01, wB01, C6);  wB23 = fma2(tB23, wB23, C6);
      wA01 = fma2(tA01, wA01, CH);  wA23 = fma2(tA23, wA23, CH);
      wB01 = fma2(tB01, wB01, CH);  wB23 = fma2(tB23, wB23, CH);
      wA01 = fma2(tA01, wA01, C1);  wA23 = fma2(tA23, wA23, C1);
      wB01 = fma2(tB01, wB01, C1);  wB23 = fma2(tB23, wB23, C1);
      u64 uA01 = mul2(tA01, wA01);
      u64 uA23 = mul2(tA23, wA23);
      u64 uB01 = mul2(tB01, wB01);
      u64 uB23 = mul2(tB23, wB23);
      lA01 = add2(lA01, uA01);
      lA23 = add2(lA23, uA23);
      lB01 = add2(lB01, uB01);
      lB23 = add2(lB23, uB23);

      // P -> bf16 A fragment (register chaining, no smem)
      uint32_t pa[4];
      pa[0] = cvt_bf16x2(uA01);   // (gid,   k 2tig..)
      pa[1] = cvt_bf16x2(uA23);   // (gid+8, k 2tig..)
      pa[2] = cvt_bf16x2(uB01);   // (gid,   k 8+2tig..)
      pa[3] = cvt_bf16x2(uB23);   // (gid+8, k 8+2tig..)

      mma_bf16(oa0, pa, vv[0], vv[1]);   // dims 0-7
      mma_bf16(oa1, pa, vv[2], vv[3]);   // dims 8-15
    }

    if (kb < 24){
      uint32_t d = dstKh + (uint32_t)(((kb+1) & 1)*4096);
      split_store(d, d + 2048, n0, n1);
    }
    __syncthreads();
  }

  // ---- epilogue: l row sums, normalize, add M0, store ----
  float2 fA01 = unpack2(lA01), fA23 = unpack2(lA23);
  float2 fB01 = unpack2(lB01), fB23 = unpack2(lB23);
  float lr0 = fA01.x + fA01.y + fB01.x + fB01.y;
  float lr8 = fA23.x + fA23.y + fB23.x + fB23.y;
  lr0 += __shfl_xor_sync(0xffffffffu, lr0, 1);
  lr0 += __shfl_xor_sync(0xffffffffu, lr0, 2);
  lr8 += __shfl_xor_sync(0xffffffffu, lr8, 1);
  lr8 += __shfl_xor_sync(0xffffffffu, lr8, 2);
  float inv0 = 1.0f / (1600.0f + lr0);
  float inv8 = 1.0f / (1600.0f + lr8);

  const float* m0p = g_m0 + (b*NHEAD + h)*16;
  float* outb = g_attn + (b*HW + qbase)*DM + h*DH;
  float* oas[2] = {oa0, oa1};
  #pragma unroll
  for (int nt=0; nt<2; nt++){
    int d0 = nt*8 + 2*tig;
    float m0a = m0p[d0], m0b = m0p[d0+1];
    outb[(gid  )*DM + d0    ] = (oas[nt][0] + m0a) * inv0;
    outb[(gid  )*DM + d0 + 1] = (oas[nt][1] + m0b) * inv0;
    outb[(gid+8)*DM + d0    ] = (oas[nt][2] + m0a) * inv8;
    outb[(gid+8)*DM + d0 + 1] = (oas[nt][3] + m0b) * inv8;
  }
}

// ---------------- K4: img_out = attn @ W2 + b2, transposed write + GeM partials
__global__ __launch_bounds__(256) void gemm2_kernel(const float* __restrict__ W2,
                                                    const float* __restrict__ b2,
                                                    float* __restrict__ img_out){
  __shared__ float As[64][33];
  __shared__ float Ws[32][128];
  __shared__ float colsum[128];
  int tile = blockIdx.x, ct = blockIdx.y;
  int b = tile / 25, pbase = (tile % 25) * 64;
  int tid = threadIdx.x, rgrp = tid >> 5, lane = tid & 31;
  if (tid < 128) colsum[tid] = 0.f;
  float acc[8][4];
  #pragma unroll
  for (int i=0;i<8;i++){ acc[i][0]=0.f; acc[i][1]=0.f; acc[i][2]=0.f; acc[i][3]=0.f; }

  for (int kt=0; kt<4; kt++){
    __syncthreads();
    #pragma unroll
    for (int it=0; it<2; it++){
      int idx = tid + it*256;
      int k4 = idx & 7, r = idx >> 3;
      float4 v = *(const float4*)(g_attn + (tile*64 + r)*DM + kt*32 + k4*4);
      As[r][k4*4+0]=v.x; As[r][k4*4+1]=v.y; As[r][k4*4+2]=v.z; As[r][k4*4+3]=v.w;
    }
    #pragma unroll
    for (int it=0; it<4; it++){
      int idx = tid + it*256;
      int c4 = idx & 31, k = idx >> 5;
      *(float4*)&Ws[k][c4*4] = *(const float4*)(W2 + (kt*32+k)*CI + ct*128 + c4*4);
    }
    __syncthreads();
    #pragma unroll 8
    for (int k=0;k<32;k++){
      float4 w = *(float4*)&Ws[k][lane*4];
      #pragma unroll
      for (int i=0;i<8;i++){
        float a = As[rgrp*8+i][k];
        acc[i][0] = fmaf(a, w.x, acc[i][0]);
        acc[i][1] = fmaf(a, w.y, acc[i][1]);
        acc[i][2] = fmaf(a, w.z, acc[i][2]);
        acc[i][3] = fmaf(a, w.w, acc[i][3]);
      }
    }
  }
  float4 bb = *(const float4*)(b2 + ct*128 + lane*4);
  float bv[4] = {bb.x, bb.y, bb.z, bb.w};
  #pragma unroll
  for (int j=0;j<4;j++){
    float part = 0.f; float vs[8];
    #pragma unroll
    for (int i=0;i<8;i++){
      float v = acc[i][j] + bv[j];
      vs[i] = v;
      float c = fmaxf(v, 1e-6f);
      part = fmaf(c*c, c, part);
    }
    atomicAdd(&colsum[lane*4+j], part);
    int cg = ct*128 + lane*4 + j;
    float* dst = img_out + b*CI*HW + cg*HW + pbase + rgrp*8;
    *(float4*)(dst)     = make_float4(vs[0],vs[1],vs[2],vs[3]);
    *(float4*)(dst + 4) = make_float4(vs[4],vs[5],vs[6],vs[7]);
  }
  __syncthreads();
  if (tid < 128) atomicAdd(&g_imgacc[b*CI + ct*128 + tid], colsum[tid]);
}

// ---------------- K7: cloud l2norm + segmented clamp^3 sum -------------------
__global__ __launch_bounds__(256) void cloud_kernel(const float* __restrict__ cf,
                                                    const int* __restrict__ bids,
                                                    float* __restrict__ cloud_out){
  __shared__ float sseg[NB*DM];
  __shared__ float scnt[NB];
  int tid = threadIdx.x;
  for (int i=tid; i<NB*DM; i+=256) sseg[i] = 0.f;
  if (tid < NB) scnt[tid] = 0.f;
  __syncthreads();
  int w = tid >> 5, lane = tid & 31;
  int rbase = blockIdx.x*256 + w*32;
  for (int i=0;i<32;i++){
    int row = rbase + i;
    int bid = bids[row];
    float4 v = *(const float4*)(cf + row*DM + lane*4);
    float sq = v.x*v.x + v.y*v.y + v.z*v.z + v.w*v.w;
    #pragma unroll
    for (int off=16; off; off>>=1) sq += __shfl_xor_sync(0xffffffffu, sq, off);
    float inv = 1.0f / fmaxf(sqrtf(sq), 1e-12f);
    float x0=v.x*inv, x1=v.y*inv, x2=v.z*inv, x3=v.w*inv;
    *(float4*)(cloud_out + row*DM + lane*4) = make_float4(x0,x1,x2,x3);
    float c0=fmaxf(x0,1e-6f), c1=fmaxf(x1,1e-6f), c2=fmaxf(x2,1e-6f), c3=fmaxf(x3,1e-6f);
    float* sp = sseg + bid*DM + lane*4;
    atomicAdd(sp+0, c0*c0*c0);
    atomicAdd(sp+1, c1*c1*c1);
    atomicAdd(sp+2, c2*c2*c2);
    atomicAdd(sp+3, c3*c3*c3);
    if (lane == 0) atomicAdd(&scnt[bid], 1.0f);
  }
  __syncthreads();
  for (int i=tid; i<NB*DM; i+=256) atomicAdd(&g_seg[i], sseg[i]);
  if (tid < NB) atomicAdd(&g_cnt[tid], scnt[tid]);
}

// ---------------- K8: finalize GeM outputs ----------------
__global__ void finalize_kernel(float* __restrict__ image_gem, float* __restrict__ cloud_gem){
  int i = blockIdx.x*256 + threadIdx.x;
  if (i < NB*CI) image_gem[i] = cbrtf(g_imgacc[i] * (1.0f/1600.0f));
  if (i < NB*DM) cloud_gem[i] = cbrtf(g_seg[i] / fmaxf(g_cnt[i>>7], 1.0f));
}

// ---------------- launch ----------------
extern "C" void kernel_launch(void* const* d_in, const int* in_sizes, int n_in,
                              void* d_out, int out_size){
  const float* img  = (const float*)d_in[0];
  const float* cf   = (const float*)d_in[1];
  const int*   bids = (const int*)  d_in[2];
  const float* W1   = (const float*)d_in[3];
  const float* b1   = (const float*)d_in[4];
  const float* W2   = (const float*)d_in[5];
  const float* b2   = (const float*)d_in[6];

  float* out       = (float*)d_out;
  float* img_out   = out;                                  // 8*256*1600
  float* cloud_out = out + (size_t)NB*CI*HW;               // 32768*128
  float* image_gem = cloud_out + (size_t)NCLOUD*DM;        // 2048
  float* cloud_gem = image_gem + NB*CI;                    // 1024

  zero_kernel<<<8, 256>>>();
  gemm1_kernel<<<200, 256>>>(img, W1, b1);
  m0_kernel<<<NB*NHEAD, 128>>>();
  attn_bf16_kernel<<<dim3(25, NHEAD, NB), 128>>>();
  gemm2_kernel<<<dim3(200, 2), 256>>>(W2, b2, img_out);
  cloud_kernel<<<NCLOUD/256, 256>>>(cf, bids, cloud_out);
  finalize_kernel<<<8, 256>>>(image_gem, cloud_gem);
}

// round 6
// speedup vs baseline: 2.7470x; 1.1709x over previous
#include <cuda_runtime.h>
#include <cuda_bf16.h>
#include <cstdint>

// ---------------- constants ----------------
#define NB      8
#define CI      256
#define HW      1600
#define DM      128
#define NHEAD   8
#define DH      16
#define NROWS   (NB*HW)        // 12800
#define NCLOUD  32768

// ---------------- device scratch ----------------
__device__ float g_tok [NROWS*DM];     // l2-normalized image tokens
__device__ float g_attn[NROWS*DM];     // attention output
__device__ float g_m0  [NB*NHEAD*DH];  // per (b,h) sum of v over keys
__device__ float g_imgacc[NB*CI];
__device__ float g_seg  [NB*DM];
__device__ float g_cnt  [NB];

typedef unsigned long long u64;

// ---------------- packed f32x2 helpers ----------------
__device__ __forceinline__ u64 fma2(u64 a, u64 b, u64 c){
  u64 d; asm("fma.rn.f32x2 %0, %1, %2, %3;" : "=l"(d) : "l"(a), "l"(b), "l"(c)); return d;
}
__device__ __forceinline__ u64 mul2(u64 a, u64 b){
  u64 d; asm("mul.rn.f32x2 %0, %1, %2;" : "=l"(d) : "l"(a), "l"(b)); return d;
}
__device__ __forceinline__ u64 add2(u64 a, u64 b){
  u64 d; asm("add.rn.f32x2 %0, %1, %2;" : "=l"(d) : "l"(a), "l"(b)); return d;
}
__device__ __forceinline__ u64 pack2(float x, float y){
  u64 d; asm("mov.b64 %0, {%1, %2};" : "=l"(d) : "f"(x), "f"(y)); return d;
}
__device__ __forceinline__ float2 unpack2(u64 u){
  float2 f; asm("mov.b64 {%0, %1}, %2;" : "=f"(f.x), "=f"(f.y) : "l"(u)); return f;
}

// bf16x2 pack: lower = f.x, upper = f.y
__device__ __forceinline__ uint32_t cvt_bf16x2(u64 p){
  float2 f = unpack2(p);
  uint32_t r;
  asm("cvt.rn.bf16x2.f32 %0, %1, %2;" : "=r"(r) : "f"(f.y), "f"(f.x));
  return r;
}
__device__ __forceinline__ uint32_t cvt_bf16x2_ff(float lo, float hi){
  uint32_t r;
  asm("cvt.rn.bf16x2.f32 %0, %1, %2;" : "=r"(r) : "f"(hi), "f"(lo));
  return r;
}
__device__ __forceinline__ uint32_t packbf(__nv_bfloat16 a, __nv_bfloat16 b){
  __nv_bfloat162 t(a, b);
  return *reinterpret_cast<uint32_t*>(&t);
}

// ---------------- mma / ldmatrix helpers ----------------
__device__ __forceinline__ void mma_bf16(float* c, const uint32_t* a, uint32_t b0, uint32_t b1){
  asm volatile("mma.sync.aligned.m16n8k16.row.col.f32.bf16.bf16.f32 "
      "{%0,%1,%2,%3}, {%4,%5,%6,%7}, {%8,%9}, {%0,%1,%2,%3};"
      : "+f"(c[0]), "+f"(c[1]), "+f"(c[2]), "+f"(c[3])
      : "r"(a[0]), "r"(a[1]), "r"(a[2]), "r"(a[3]), "r"(b0), "r"(b1));
}
__device__ __forceinline__ void ldsm4(uint32_t addr, uint32_t* r){
  asm volatile("ldmatrix.sync.aligned.m8n8.x4.shared.b16 {%0,%1,%2,%3}, [%4];"
      : "=r"(r[0]), "=r"(r[1]), "=r"(r[2]), "=r"(r[3]) : "r"(addr));
}
__device__ __forceinline__ void ldsm4t(uint32_t addr, uint32_t* r){
  asm volatile("ldmatrix.sync.aligned.m8n8.x4.trans.shared.b16 {%0,%1,%2,%3}, [%4];"
      : "=r"(r[0]), "=r"(r[1]), "=r"(r[2]), "=r"(r[3]) : "r"(addr));
}
__device__ __forceinline__ void sts64(uint32_t addr, uint32_t r0, uint32_t r1){
  asm volatile("st.shared.v2.b32 [%0], {%1,%2};" :: "r"(addr), "r"(r0), "r"(r1));
}

// ---------------- K0: zero accumulators ----------------
__global__ void zero_kernel(){
  int i = blockIdx.x*256 + threadIdx.x;
  if (i < NB*CI) g_imgacc[i] = 0.f;
  if (i < NB*DM) g_seg[i]    = 0.f;
  if (i < NB)    g_cnt[i]    = 0.f;
}

// ---------------- K1: x = einsum(bchw,cd)+b1, rowwise l2norm -> g_tok --------
__global__ __launch_bounds__(256) void gemm1_kernel(const float* __restrict__ img,
                                                    const float* __restrict__ W1,
                                                    const float* __restrict__ b1){
  __shared__ float As[32][64];
  __shared__ float Ws[32][128];
  int tile = blockIdx.x;
  int b = tile / 25;
  int pbase = (tile % 25) * 64;
  const float* Ab = img + b*CI*HW + pbase;
  int tid = threadIdx.x;
  int rgrp = tid >> 5, lane = tid & 31;
  float acc[8][4];
  #pragma unroll
  for (int i=0;i<8;i++){ acc[i][0]=0.f; acc[i][1]=0.f; acc[i][2]=0.f; acc[i][3]=0.f; }

  for (int kt=0; kt<8; kt++){
    __syncthreads();
    #pragma unroll
    for (int it=0; it<8; it++){
      int idx = tid + it*256;
      int r = idx & 63, k = idx >> 6;
      As[k][r] = Ab[(kt*32+k)*HW + r];
    }
    #pragma unroll
    for (int it=0; it<4; it++){
      int idx = tid + it*256;
      int c4 = idx & 31, k = idx >> 5;
      *(float4*)&Ws[k][c4*4] = *(const float4*)(W1 + (kt*32+k)*DM + c4*4);
    }
    __syncthreads();
    #pragma unroll 8
    for (int k=0;k<32;k++){
      float4 w  = *(float4*)&Ws[k][lane*4];
      float4 a0 = *(float4*)&As[k][rgrp*8];
      float4 a1 = *(float4*)&As[k][rgrp*8+4];
      float a[8] = {a0.x,a0.y,a0.z,a0.w,a1.x,a1.y,a1.z,a1.w};
      #pragma unroll
      for (int i=0;i<8;i++){
        acc[i][0] = fmaf(a[i], w.x, acc[i][0]);
        acc[i][1] = fmaf(a[i], w.y, acc[i][1]);
        acc[i][2] = fmaf(a[i], w.z, acc[i][2]);
        acc[i][3] = fmaf(a[i], w.w, acc[i][3]);
      }
    }
  }
  float4 bb = *(const float4*)(b1 + lane*4);
  int Rbase = tile*64 + rgrp*8;
  #pragma unroll
  for (int i=0;i<8;i++){
    float x0 = acc[i][0]+bb.x, x1 = acc[i][1]+bb.y, x2 = acc[i][2]+bb.z, x3 = acc[i][3]+bb.w;
    float sq = x0*x0 + x1*x1 + x2*x2 + x3*x3;
    #pragma unroll
    for (int off=16; off; off>>=1) sq += __shfl_xor_sync(0xffffffffu, sq, off);
    float inv = 1.0f / fmaxf(sqrtf(sq), 1e-12f);
    *(float4*)(g_tok + (Rbase+i)*DM + lane*4) = make_float4(x0*inv, x1*inv, x2*inv, x3*inv);
  }
}

// ---------------- K2: M0[b,h,d] = sum over keys of v ----------------
__global__ __launch_bounds__(128) void m0_kernel(){
  int bh = blockIdx.x;
  const float* base = g_tok + (bh>>3)*HW*DM + (bh&7)*DH;
  __shared__ float red[128];
  int tid = threadIdx.x;
  int d = tid & 15, seg = tid >> 4;
  float s = 0.f;
  for (int t = seg; t < HW; t += 8) s += base[t*DM + d];
  red[tid] = s;
  __syncthreads();
  if (tid < 16){
    float a = 0.f;
    #pragma unroll
    for (int i=0;i<8;i++) a += red[tid + i*16];
    g_m0[bh*16 + tid] = a;
  }
}

// ---------------- K3: attention, q-exact/k-bf16 scores, 8 warps/CTA ----------
// S = qh*kh + ql*kh (q split exact, k bf16). u = expm1(S) deg-4.
// P(bf16, regs) -> PV mma. O = M0 + U*V, l = 1600 + sum u.
// smem buffer: plane A (dims 0-7) @0, plane B (dims 8-15) @1024; 2 buffers.
__global__ __launch_bounds__(256) void attn_bf16_kernel(){
  __shared__ __align__(1024) unsigned char sbuf[2][2048];
  int b = blockIdx.z, h = blockIdx.y;
  int tid = threadIdx.x, w = tid >> 5, lane = tid & 31;
  int gid = lane >> 2, tig = lane & 3;
  const float* base = g_tok + b*HW*DM + h*DH;
  int qb0 = blockIdx.x*128 + w*16;
  bool wstore = (qb0 < HW);
  int qbase = wstore ? qb0 : (HW - 16);

  // ---- Q fragments, scaled by 0.25 (exact), split hi/lo ----
  uint32_t qh[4], ql[4];
  #pragma unroll
  for (int i=0;i<4;i++){
    int row = qbase + gid + (i & 1)*8;
    int col = 2*tig + (i >> 1)*8;
    float2 v = *(const float2*)(base + row*DM + col);
    float x0 = v.x*0.25f, x1 = v.y*0.25f;
    __nv_bfloat16 h0 = __float2bfloat16_rn(x0);
    __nv_bfloat16 h1 = __float2bfloat16_rn(x1);
    float r0 = x0 - __bfloat162float(h0);
    float r1 = x1 - __bfloat162float(h1);
    qh[i] = packbf(h0, h1);
    ql[i] = packbf(__float2bfloat16_rn(r0), __float2bfloat16_rn(r1));
  }

  float oa0[4] = {0.f,0.f,0.f,0.f};
  float oa1[4] = {0.f,0.f,0.f,0.f};
  u64 lA01 = 0ULL, lA23 = 0ULL, lB01 = 0ULL, lB23 = 0ULL;

  const u64 C24 = pack2(4.1666667e-2f, 4.1666667e-2f);
  const u64 C6  = pack2(1.6666667e-1f, 1.6666667e-1f);
  const u64 CH  = pack2(0.5f, 0.5f);
  const u64 C1  = pack2(1.0f, 1.0f);

  // ---- ldmatrix per-lane base addresses ----
  uint32_t sb0 = (uint32_t)__cvta_generic_to_shared(&sbuf[0][0]);
  int r7 = lane & 7;
  uint32_t aScore = sb0 + (uint32_t)((r7 + ((lane >> 4) & 1)*8)*16 + ((lane >> 3) & 1)*1024);
  uint32_t aPV    = sb0 + (uint32_t)((r7 + ((lane >> 3) & 1)*8)*16 + ((lane >> 4) & 1)*1024);

  // ---- tile store addressing: 256 threads, 1 float4 each ----
  int key = tid >> 2, quarter = tid & 3;
  const float* gsrc = base + key*DM + quarter*4;
  uint32_t dstK = sb0 + (uint32_t)((quarter >> 1)*1024 + key*16 + (quarter & 1)*8);

  // prologue: tile 0 -> buffer 0
  {
    float4 v = *(const float4*)(gsrc);
    sts64(dstK, cvt_bf16x2_ff(v.x, v.y), cvt_bf16x2_ff(v.z, v.w));
  }
  __syncthreads();

  for (int kb=0; kb<25; kb++){
    float4 nv;
    if (kb < 24) nv = *(const float4*)(gsrc + (kb+1)*64*DM);
    uint32_t bufoff = (uint32_t)((kb & 1)*2048);
    uint32_t aS = aScore + bufoff;
    uint32_t aP = aPV + bufoff;

    #pragma unroll
    for (int ck=0; ck<4; ck++){
      uint32_t off = (uint32_t)(ck*256);
      uint32_t kh[4], vv[4];
      ldsm4 (aS + off, kh);
      ldsm4t(aP + off, vv);

      float cA[4] = {0.f,0.f,0.f,0.f};
      float cB[4] = {0.f,0.f,0.f,0.f};
      mma_bf16(cA, qh, kh[0], kh[1]);
      mma_bf16(cA, ql, kh[0], kh[1]);
      mma_bf16(cB, qh, kh[2], kh[3]);
      mma_bf16(cB, ql, kh[2], kh[3]);

      // u = expm1(t), deg-4, packed pairs
      u64 tA01 = pack2(cA[0], cA[1]);
      u64 tA23 = pack2(cA[2], cA[3]);
      u64 tB01 = pack2(cB[0], cB[1]);
      u64 tB23 = pack2(cB[2], cB[3]);
      u64 wA01 = fma2(tA01, C24, C6);
      u64 wA23 = fma2(tA23, C24, C6);
      u64 wB01 = fma2(tB01, C24, C6);
      u64 wB23 = fma2(tB23, C24, C6);
      wA01 = fma2(tA01, wA01, CH);  wA23 = fma2(tA23, wA23, CH);
      wB01 = fma2(tB01, wB01, CH);  wB23 = fma2(tB23, wB23, CH);
      wA01 = fma2(tA01, wA01, C1);  wA23 = fma2(tA23, wA23, C1);
      wB01 = fma2(tB01, wB01, C1);  wB23 = fma2(tB23, wB23, C1);
      u64 uA01 = mul2(tA01, wA01);
      u64 uA23 = mul2(tA23, wA23);
      u64 uB01 = mul2(tB01, wB01);
      u64 uB23 = mul2(tB23, wB23);
      lA01 = add2(lA01, uA01);
      lA23 = add2(lA23, uA23);
      lB01 = add2(lB01, uB01);
      lB23 = add2(lB23, uB23);

      // P -> bf16 A fragment (register chaining)
      uint32_t pa[4];
      pa[0] = cvt_bf16x2(uA01);
      pa[1] = cvt_bf16x2(uA23);
      pa[2] = cvt_bf16x2(uB01);
      pa[3] = cvt_bf16x2(uB23);

      mma_bf16(oa0, pa, vv[0], vv[1]);   // dims 0-7
      mma_bf16(oa1, pa, vv[2], vv[3]);   // dims 8-15
    }

    if (kb < 24){
      uint32_t d = dstK + (uint32_t)(((kb+1) & 1)*2048);
      sts64(d, cvt_bf16x2_ff(nv.x, nv.y), cvt_bf16x2_ff(nv.z, nv.w));
    }
    __syncthreads();
  }

  // ---- epilogue ----
  float2 fA01 = unpack2(lA01), fA23 = unpack2(lA23);
  float2 fB01 = unpack2(lB01), fB23 = unpack2(lB23);
  float lr0 = fA01.x + fA01.y + fB01.x + fB01.y;
  float lr8 = fA23.x + fA23.y + fB23.x + fB23.y;
  lr0 += __shfl_xor_sync(0xffffffffu, lr0, 1);
  lr0 += __shfl_xor_sync(0xffffffffu, lr0, 2);
  lr8 += __shfl_xor_sync(0xffffffffu, lr8, 1);
  lr8 += __shfl_xor_sync(0xffffffffu, lr8, 2);
  float inv0 = 1.0f / (1600.0f + lr0);
  float inv8 = 1.0f / (1600.0f + lr8);

  if (wstore){
    const float* m0p = g_m0 + (b*NHEAD + h)*16;
    float* outb = g_attn + (b*HW + qbase)*DM + h*DH;
    float* oas[2] = {oa0, oa1};
    #pragma unroll
    for (int nt=0; nt<2; nt++){
      int d0 = nt*8 + 2*tig;
      float m0a = m0p[d0], m0b = m0p[d0+1];
      outb[(gid  )*DM + d0    ] = (oas[nt][0] + m0a) * inv0;
      outb[(gid  )*DM + d0 + 1] = (oas[nt][1] + m0b) * inv0;
      outb[(gid+8)*DM + d0    ] = (oas[nt][2] + m0a) * inv8;
      outb[(gid+8)*DM + d0 + 1] = (oas[nt][3] + m0b) * inv8;
    }
  }
}

// ---------------- K4: img_out = attn @ W2 + b2, transposed write + GeM partials
__global__ __launch_bounds__(256) void gemm2_kernel(const float* __restrict__ W2,
                                                    const float* __restrict__ b2,
                                                    float* __restrict__ img_out){
  __shared__ float As[64][33];
  __shared__ float Ws[32][128];
  __shared__ float colsum[128];
  int tile = blockIdx.x, ct = blockIdx.y;
  int b = tile / 25, pbase = (tile % 25) * 64;
  int tid = threadIdx.x, rgrp = tid >> 5, lane = tid & 31;
  if (tid < 128) colsum[tid] = 0.f;
  float acc[8][4];
  #pragma unroll
  for (int i=0;i<8;i++){ acc[i][0]=0.f; acc[i][1]=0.f; acc[i][2]=0.f; acc[i][3]=0.f; }

  for (int kt=0; kt<4; kt++){
    __syncthreads();
    #pragma unroll
    for (int it=0; it<2; it++){
      int idx = tid + it*256;
      int k4 = idx & 7, r = idx >> 3;
      float4 v = *(const float4*)(g_attn + (tile*64 + r)*DM + kt*32 + k4*4);
      As[r][k4*4+0]=v.x; As[r][k4*4+1]=v.y; As[r][k4*4+2]=v.z; As[r][k4*4+3]=v.w;
    }
    #pragma unroll
    for (int it=0; it<4; it++){
      int idx = tid + it*256;
      int c4 = idx & 31, k = idx >> 5;
      *(float4*)&Ws[k][c4*4] = *(const float4*)(W2 + (kt*32+k)*CI + ct*128 + c4*4);
    }
    __syncthreads();
    #pragma unroll 8
    for (int k=0;k<32;k++){
      float4 w = *(float4*)&Ws[k][lane*4];
      #pragma unroll
      for (int i=0;i<8;i++){
        float a = As[rgrp*8+i][k];
        acc[i][0] = fmaf(a, w.x, acc[i][0]);
        acc[i][1] = fmaf(a, w.y, acc[i][1]);
        acc[i][2] = fmaf(a, w.z, acc[i][2]);
        acc[i][3] = fmaf(a, w.w, acc[i][3]);
      }
    }
  }
  float4 bb = *(const float4*)(b2 + ct*128 + lane*4);
  float bv[4] = {bb.x, bb.y, bb.z, bb.w};
  #pragma unroll
  for (int j=0;j<4;j++){
    float part = 0.f; float vs[8];
    #pragma unroll
    for (int i=0;i<8;i++){
      float v = acc[i][j] + bv[j];
      vs[i] = v;
      float c = fmaxf(v, 1e-6f);
      part = fmaf(c*c, c, part);
    }
    atomicAdd(&colsum[lane*4+j], part);
    int cg = ct*128 + lane*4 + j;
    float* dst = img_out + b*CI*HW + cg*HW + pbase + rgrp*8;
    *(float4*)(dst)     = make_float4(vs[0],vs[1],vs[2],vs[3]);
    *(float4*)(dst + 4) = make_float4(vs[4],vs[5],vs[6],vs[7]);
  }
  __syncthreads();
  if (tid < 128) atomicAdd(&g_imgacc[b*CI + ct*128 + tid], colsum[tid]);
}

// ---------------- K7: cloud l2norm + segmented clamp^3 sum -------------------
// 512 blocks, 8 rows per warp (latency-bound fix: >3 CTAs/SM)
__global__ __launch_bounds__(256) void cloud_kernel(const float* __restrict__ cf,
                                                    const int* __restrict__ bids,
                                                    float* __restrict__ cloud_out){
  __shared__ float sseg[NB*DM];
  __shared__ float scnt[NB];
  int tid = threadIdx.x;
  for (int i=tid; i<NB*DM; i+=256) sseg[i] = 0.f;
  if (tid < NB) scnt[tid] = 0.f;
  __syncthreads();
  int w = tid >> 5, lane = tid & 31;
  int rbase = blockIdx.x*64 + w*8;
  #pragma unroll
  for (int i=0;i<8;i++){
    int row = rbase + i;
    int bid = bids[row];
    float4 v = *(const float4*)(cf + row*DM + lane*4);
    float sq = v.x*v.x + v.y*v.y + v.z*v.z + v.w*v.w;
    #pragma unroll
    for (int off=16; off; off>>=1) sq += __shfl_xor_sync(0xffffffffu, sq, off);
    float inv = 1.0f / fmaxf(sqrtf(sq), 1e-12f);
    float x0=v.x*inv, x1=v.y*inv, x2=v.z*inv, x3=v.w*inv;
    *(float4*)(cloud_out + row*DM + lane*4) = make_float4(x0,x1,x2,x3);
    float c0=fmaxf(x0,1e-6f), c1=fmaxf(x1,1e-6f), c2=fmaxf(x2,1e-6f), c3=fmaxf(x3,1e-6f);
    float* sp = sseg + bid*DM + lane*4;
    atomicAdd(sp+0, c0*c0*c0);
    atomicAdd(sp+1, c1*c1*c1);
    atomicAdd(sp+2, c2*c2*c2);
    atomicAdd(sp+3, c3*c3*c3);
    if (lane == 0) atomicAdd(&scnt[bid], 1.0f);
  }
  __syncthreads();
  for (int i=tid; i<NB*DM; i+=256) atomicAdd(&g_seg[i], sseg[i]);
  if (tid < NB) atomicAdd(&g_cnt[tid], scnt[tid]);
}

// ---------------- K8: finalize GeM outputs ----------------
__global__ void finalize_kernel(float* __restrict__ image_gem, float* __restrict__ cloud_gem){
  int i = blockIdx.x*256 + threadIdx.x;
  if (i < NB*CI) image_gem[i] = cbrtf(g_imgacc[i] * (1.0f/1600.0f));
  if (i < NB*DM) cloud_gem[i] = cbrtf(g_seg[i] / fmaxf(g_cnt[i>>7], 1.0f));
}

// ---------------- launch ----------------
extern "C" void kernel_launch(void* const* d_in, const int* in_sizes, int n_in,
                              void* d_out, int out_size){
  const float* img  = (const float*)d_in[0];
  const float* cf   = (const float*)d_in[1];
  const int*   bids = (const int*)  d_in[2];
  const float* W1   = (const float*)d_in[3];
  const float* b1   = (const float*)d_in[4];
  const float* W2   = (const float*)d_in[5];
  const float* b2   = (const float*)d_in[6];

  float* out       = (float*)d_out;
  float* img_out   = out;                                  // 8*256*1600
  float* cloud_out = out + (size_t)NB*CI*HW;               // 32768*128
  float* image_gem = cloud_out + (size_t)NCLOUD*DM;        // 2048
  float* cloud_gem = image_gem + NB*CI;                    // 1024

  zero_kernel<<<8, 256>>>();
  gemm1_kernel<<<200, 256>>>(img, W1, b1);
  m0_kernel<<<NB*NHEAD, 128>>>();
  attn_bf16_kernel<<<dim3(13, NHEAD, NB), 256>>>();
  gemm2_kernel<<<dim3(200, 2), 256>>>(W2, b2, img_out);
  cloud_kernel<<<512, 256>>>(cf, bids, cloud_out);
  finalize_kernel<<<8, 256>>>(image_gem, cloud_gem);
}